// round 7
// baseline (speedup 1.0000x reference)
#include <cuda_runtime.h>
#include <cuda_bf16.h>
#include <cstdint>

// Problem constants
#define BATCH   8
#define NELEM   262144          // 2^18
#define NSHIFT  18
#define TOPK    6000
#define NOUT    1000
#define NMS_THR 0.7f
#define BINS    65536           // scores < 1.0 => (bits>>14) <= 65024
#define BIN_SHIFT 14
#define SORTN   8192
#define NPAD    6016            // 94 * 64
#define NPAD2   (NPAD + 40)     // prefetch overrun padding
#define NWORDS  94
#define RC4N    24              // ceil(94/4)

typedef unsigned long long u64;
typedef unsigned int u32;

// ---------------- static device scratch ----------------
__device__ u32 g_hist[BATCH * BINS];             // 2 MB
__device__ u64 g_main[BATCH * TOPK];
__device__ u64 g_bnd[BATCH * NELEM];
__device__ u32 g_cnt_main[BATCH];
__device__ u32 g_cnt_bnd[BATCH];
__device__ u32 g_pbin[BATCH];

__device__ float4 g_sbox[BATCH][NPAD];           // sorted, decoded, clipped boxes
__device__ float  g_area[BATCH][NPAD];
__device__ u64    g_mask[BATCH][NPAD2][NWORDS];  // suppression bitmasks

// ---------------- kernel 0: zero scratch (vectorized) ----------------
__global__ void k_zero(){
    u32 i = blockIdx.x * blockDim.x + threadIdx.x;        // over uint4 groups
    ((uint4*)g_hist)[i] = make_uint4(0u, 0u, 0u, 0u);
    if (i < BATCH) { g_cnt_main[i] = 0; g_cnt_bnd[i] = 0; }
}

// ---------------- kernel 1: histogram (8 elems/thread) ----------------
__global__ void k_hist(const float4* __restrict__ cls4) {
    u32 i = blockIdx.x * blockDim.x + threadIdx.x;   // group of 8 elements
    float4 p0 = cls4[4 * i];
    float4 p1 = cls4[4 * i + 1];
    float4 p2 = cls4[4 * i + 2];
    float4 p3 = cls4[4 * i + 3];
    u32 b = (i << 3) >> NSHIFT;                      // all 8 in same batch
    u32* h = &g_hist[b * BINS];
    float sc[8] = {p0.y, p0.w, p1.y, p1.w, p2.y, p2.w, p3.y, p3.w};
    #pragma unroll
    for (int k = 0; k < 8; k++) {
        u32 bin = min(__float_as_uint(sc[k]) >> BIN_SHIFT, (u32)(BINS - 1));
        atomicAdd(&h[bin], 1u);
    }
}

// ---------------- kernel 2: find per-batch threshold bin ----------------
__global__ void __launch_bounds__(1024) k_select() {
    int b = blockIdx.x;
    int tid = threadIdx.x;
    const int CH = BINS / 1024;                  // 64 bins per thread
    const u32* hist = &g_hist[b * BINS];

    u32 mysum = 0;
    int base = tid * CH;
    #pragma unroll 8
    for (int k = 0; k < CH; k++) mysum += hist[base + k];

    __shared__ u32 ss[1024];
    ss[tid] = mysum;
    __syncthreads();
    for (int off = 1; off < 1024; off <<= 1) {
        u32 v = (tid + off < 1024) ? ss[tid + off] : 0u;
        __syncthreads();
        ss[tid] += v;
        __syncthreads();
    }
    u32 A = ss[tid] - mysum;                     // strictly-above count
    if (A < TOPK && A + mysum >= TOPK) {
        u32 acc = A;
        for (int bin = base + CH - 1; bin >= base; --bin) {
            u32 h = hist[bin];
            if (acc + h >= TOPK) { g_pbin[b] = (u32)bin; break; }
            acc += h;
        }
    }
}

// ---------------- kernel 3: compaction (8 elems/thread) ----------------
__global__ void k_compact(const float4* __restrict__ cls4) {
    u32 i = blockIdx.x * blockDim.x + threadIdx.x;   // group of 8 elements
    float4 p0 = cls4[4 * i];
    float4 p1 = cls4[4 * i + 1];
    float4 p2 = cls4[4 * i + 2];
    float4 p3 = cls4[4 * i + 3];
    u32 base = i << 3;
    u32 b = base >> NSHIFT;
    u32 p = g_pbin[b];
    float sc[8] = {p0.y, p0.w, p1.y, p1.w, p2.y, p2.w, p3.y, p3.w};
    #pragma unroll
    for (int k = 0; k < 8; k++) {
        u32 bits = __float_as_uint(sc[k]);
        u32 bin = min(bits >> BIN_SHIFT, (u32)(BINS - 1));
        u32 idx = (base + k) & (NELEM - 1);
        if (bin > p) {
            u32 pos = atomicAdd(&g_cnt_main[b], 1u);
            g_main[b * TOPK + pos] = ((u64)bits << 32) | (u32)(~idx);
        } else if (bin == p) {
            u32 pos = atomicAdd(&g_cnt_bnd[b], 1u);
            g_bnd[(u32)b * NELEM + pos] = ((u64)bits << 32) | (u32)(~idx);
        }
    }
}

// ---------------- kernel 4: sort keys, decode boxes -> global ----------------
__global__ void __launch_bounds__(1024, 1)
k_sort(const float4* __restrict__ bbox, const float4* __restrict__ anchors) {
    extern __shared__ __align__(16) unsigned char smem_raw[];
    u64* keys = (u64*)smem_raw;                  // 8192 * 8 = 65536

    int b = blockIdx.x;
    int tid = threadIdx.x;
    int lane = tid & 31;
    int wid = tid >> 5;

    u32 cnt_main = g_cnt_main[b];
    u32 m = g_cnt_bnd[b];
    u32 total = cnt_main + m;

    for (u32 i = tid; i < cnt_main; i += 1024) keys[i] = g_main[b * TOPK + i];

    if (total <= SORTN) {
        for (u32 i = tid; i < m; i += 1024) keys[cnt_main + i] = g_bnd[(u32)b * NELEM + i];
        for (u32 i = total + tid; i < SORTN; i += 1024) keys[i] = 0ull;
        __syncthreads();
    } else {
        // pathological fallback: iteratively select top-r boundary keys
        for (u32 i = cnt_main + tid; i < SORTN; i += 1024) keys[i] = 0ull;
        __syncthreads();
        __shared__ u64 rk[32];
        __shared__ u32 rp[32];
        int r = TOPK - (int)cnt_main;
        for (int round = 0; round < r; ++round) {
            u64 bk = 0; u32 bp = 0;
            for (u32 i = tid; i < m; i += 1024) {
                u64 v = g_bnd[(u32)b * NELEM + i];
                if (v > bk) { bk = v; bp = i; }
            }
            for (int off = 16; off; off >>= 1) {
                u64 ok = __shfl_down_sync(0xFFFFFFFFu, bk, off);
                u32 op = __shfl_down_sync(0xFFFFFFFFu, bp, off);
                if (ok > bk) { bk = ok; bp = op; }
            }
            if (lane == 0) { rk[wid] = bk; rp[wid] = bp; }
            __syncthreads();
            if (wid == 0) {
                bk = rk[lane]; bp = rp[lane];
                for (int off = 16; off; off >>= 1) {
                    u64 ok = __shfl_down_sync(0xFFFFFFFFu, bk, off);
                    u32 op = __shfl_down_sync(0xFFFFFFFFu, bp, off);
                    if (ok > bk) { bk = ok; bp = op; }
                }
                if (lane == 0) {
                    keys[cnt_main + round] = bk;
                    g_bnd[(u32)b * NELEM + bp] = 0ull;
                }
            }
            __syncthreads();
        }
    }

    // bitonic sort descending
    for (u32 k = 2; k <= SORTN; k <<= 1) {
        for (u32 j = k >> 1; j; j >>= 1) {
            for (u32 i = tid; i < SORTN; i += 1024) {
                u32 ix = i ^ j;
                if (ix > i) {
                    u64 a = keys[i], c = keys[ix];
                    bool dirDesc = ((i & k) == 0);
                    if ((a < c) == dirDesc) { keys[i] = c; keys[ix] = a; }
                }
            }
            __syncthreads();
        }
    }

    // decode boxes for top slots, write to global (+ zero pad)
    for (int s = tid; s < NPAD; s += 1024) {
        if (s < TOPK) {
            u64 key = keys[s];
            u32 idx = ~(u32)(key & 0xFFFFFFFFull);
            u32 gi = ((u32)b << NSHIFT) + idx;
            float4 a = anchors[gi];
            float4 d = bbox[gi];
            d.x *= 0.1f; d.y *= 0.1f; d.z *= 0.2f; d.w *= 0.2f;
            float h = a.z - a.x;
            float w = a.w - a.y;
            float cy = a.x + 0.5f * h;
            float cx = a.y + 0.5f * w;
            cy = cy + d.x * h;
            cx = cx + d.y * w;
            h = h * expf(d.z);
            w = w * expf(d.w);
            float4 box;
            box.x = fminf(fmaxf(cy - 0.5f * h, 0.0f), 1.0f);
            box.y = fminf(fmaxf(cx - 0.5f * w, 0.0f), 1.0f);
            box.z = fminf(fmaxf(cy + 0.5f * h, 0.0f), 1.0f);
            box.w = fminf(fmaxf(cx + 0.5f * w, 0.0f), 1.0f);
            g_sbox[b][s] = box;
            g_area[b][s] = (box.z - box.x) * (box.w - box.y);
        } else {
            g_sbox[b][s] = make_float4(0.0f, 0.0f, 0.0f, 0.0f);
            g_area[b][s] = 0.0f;
        }
    }
}

// ---------------- kernel 5: pairwise IoU suppression bitmask ----------------
// Triangular grid: only blocks with cc >= rc4*4 are launched.
// Division-free fast path: iou > 0.7  <=>  1.7*inter > 0.7*(areaA+areaC)
// Near-threshold pairs fall back to the exact reference-order division.
__constant__ u32 c_tri[RC4N];    // prefix of live (rc4 -> first flat index)

__global__ void __launch_bounds__(256) k_mask() {
    // decode flat triangular index -> (rc4, cc)
    u32 flat = blockIdx.x;
    int rc4 = 0;
    #pragma unroll
    for (int k = 0; k < RC4N; k++) if (flat >= c_tri[k]) rc4 = k;
    int cc = (rc4 << 2) + (int)(flat - c_tri[rc4]);
    int b = blockIdx.z;

    __shared__ float4 cbox[64];
    __shared__ float  ca07[64];      // 0.7 * area
    __shared__ float  ca[64];        // exact area (fallback path)
    int t = threadIdx.x;
    int col0 = cc << 6;
    if (t < 64) {
        cbox[t] = g_sbox[b][col0 + t];
        float ar = g_area[b][col0 + t];
        ca[t] = ar;
        ca07[t] = 0.7f * ar;
    }
    __syncthreads();

    int rc = (rc4 << 2) + (t >> 6);
    if (rc > cc || rc >= NWORDS) return;
    int i = (rc << 6) + (t & 63);
    float4 a = g_sbox[b][i];
    float areaA = g_area[b][i];
    float a07 = 0.7f * areaA;

    u64 bits = 0, nearb = 0;
    if (cc != rc) {
        // off-diagonal: all 64 columns are strictly after row i
        #pragma unroll 16
        for (int j = 0; j < 64; j++) {
            float4 c = cbox[j];
            float y1 = fmaxf(a.x, c.x);
            float x1 = fmaxf(a.y, c.y);
            float y2 = fminf(a.z, c.z);
            float x2 = fminf(a.w, c.w);
            float inter = fmaxf(y2 - y1, 0.0f) * fmaxf(x2 - x1, 0.0f);
            float rhs = a07 + ca07[j];
            float d = fmaf(1.7f, inter, -rhs);
            float mg = fmaf(1e-4f, rhs, 1e-12f);
            if (d > 0.0f) bits |= (1ull << j);
            if (fabsf(d) < mg) nearb |= (1ull << j);
        }
    } else {
        #pragma unroll 16
        for (int j = 0; j < 64; j++) {
            if (col0 + j > i) {
                float4 c = cbox[j];
                float y1 = fmaxf(a.x, c.x);
                float x1 = fmaxf(a.y, c.y);
                float y2 = fminf(a.z, c.z);
                float x2 = fminf(a.w, c.w);
                float inter = fmaxf(y2 - y1, 0.0f) * fmaxf(x2 - x1, 0.0f);
                float rhs = a07 + ca07[j];
                float d = fmaf(1.7f, inter, -rhs);
                float mg = fmaf(1e-4f, rhs, 1e-12f);
                if (d > 0.0f) bits |= (1ull << j);
                if (fabsf(d) < mg) nearb |= (1ull << j);
            }
        }
    }

    // rare exact fixup (reference rounding order, IEEE div)
    while (nearb) {
        int j = __ffsll((long long)nearb) - 1;
        nearb &= nearb - 1;
        float4 c = cbox[j];
        float y1 = fmaxf(a.x, c.x);
        float x1 = fmaxf(a.y, c.y);
        float y2 = fminf(a.z, c.z);
        float x2 = fminf(a.w, c.w);
        float inter = fmaxf(y2 - y1, 0.0f) * fmaxf(x2 - x1, 0.0f);
        float denom = areaA + ca[j] - inter + 1e-9f;
        float iou = inter / denom;
        if (iou > NMS_THR) bits |= (1ull << j);
        else               bits &= ~(1ull << j);
    }

    g_mask[b][i][cc] = bits;
}

// ---------------- kernel 6: serial greedy pass over bitmasks ----------------
// Critical chain: ffs -> broadcast L1-hit LDG -> OR. Prefetch 32 rows ahead
// (>600 cycles of lead time) so row[w] is L1-resident.
__global__ void __launch_bounds__(32) k_seq(float4* __restrict__ out) {
    int b = blockIdx.x;
    int lane = threadIdx.x;

    __shared__ u64 remv[NWORDS];
    for (int r = lane; r < NWORDS; r += 32) remv[r] = 0ull;

    const float4* sb = g_sbox[b];
    float4* ob = out + b * NOUT;
    int cnt = 0;

    // warm the L1 with the first ~32 rows (24KB)
    {
        const char* pb = (const char*)&g_mask[b][0][0];
        #pragma unroll
        for (int q = 0; q < 6; q++)
            asm volatile("prefetch.global.L1 [%0];"
                         :: "l"(pb + ((u32)lane + 32u * q) * 128));
    }

    for (int w = 0; w < NWORDS && cnt < NOUT; w++) {
        __syncwarp();                                  // drain remv updates
        u64 live = (w == NWORDS - 1) ? ((1ull << 48) - 1ull) : ~0ull;
        u64 rw = (~remv[w]) & live;                    // one LDS per word

        while (cnt < NOUT && rw) {
            int bit = __ffsll((long long)rw) - 1;
            int i = (w << 6) + bit;
            const u64* row = &g_mask[b][i][0];

            if (lane == 0) ob[cnt] = sb[i];
            cnt++;

            // off critical path: fold row into remv for later words
            #pragma unroll
            for (int r = 0; r < 3; r++) {
                int j = lane + (r << 5);
                if (j < NWORDS && j > w) remv[j] |= row[j];
            }
            // prefetch rows i+1 .. i+~33 (24KB) into L1
            {
                const char* pb = (const char*)&g_mask[b][i + 1][0];
                #pragma unroll
                for (int q = 0; q < 6; q++)
                    asm volatile("prefetch.global.L1 [%0];"
                                 :: "l"(pb + ((u32)lane + 32u * q) * 128));
            }

            // critical path: broadcast load of current word, all lanes identical
            u64 mw = row[w];
            rw &= ~mw;
            rw &= ~(1ull << bit);
        }
    }

    for (int q = cnt + lane; q < NOUT; q += 32)
        ob[q] = make_float4(0.0f, 0.0f, 0.0f, 0.0f);
}

// ---------------- launch ----------------
extern "C" void kernel_launch(void* const* d_in, const int* in_sizes, int n_in,
                              void* d_out, int out_size) {
    const float4* cls4    = (const float4*)d_in[0];
    const float4* bbox    = (const float4*)d_in[1];
    const float4* anchors = (const float4*)d_in[2];
    float4* out = (float4*)d_out;

    (void)in_sizes; (void)n_in; (void)out_size;

    const int total = BATCH * NELEM;

    // triangular block index prefix (host-computed, cached across replays
    // by value equality — constant, so safe to set every launch)
    static bool tri_done = false;
    static u32 tri[RC4N];
    static u32 tri_total = 0;
    if (!tri_done) {
        u32 acc = 0;
        for (int r = 0; r < RC4N; r++) {
            tri[r] = acc;
            u32 ccs = (u32)(NWORDS - (r << 2));   // cc in [4r, 93]
            acc += ccs;
        }
        tri_total = acc;
        tri_done = true;
    }
    cudaMemcpyToSymbolAsync(c_tri, tri, sizeof(tri), 0, cudaMemcpyHostToDevice);

    k_zero<<<(BATCH * BINS / 4) / 256, 256>>>();
    k_hist<<<(total / 8) / 256, 256>>>(cls4);
    k_select<<<BATCH, 1024>>>();
    k_compact<<<(total / 8) / 256, 256>>>(cls4);

    cudaFuncSetAttribute(k_sort, cudaFuncAttributeMaxDynamicSharedMemorySize, 65536);
    k_sort<<<BATCH, 1024, 65536>>>(bbox, anchors);

    dim3 mgrid(tri_total, 1, BATCH);
    k_mask<<<mgrid, 256>>>();

    k_seq<<<BATCH, 32>>>(out);
}

// round 9
// speedup vs baseline: 1.2226x; 1.2226x over previous
#include <cuda_runtime.h>
#include <cuda_bf16.h>
#include <cstdint>

// Problem constants
#define BATCH   8
#define NELEM   262144          // 2^18
#define NSHIFT  18
#define TOPK    6000
#define NOUT    1000
#define NMS_THR 0.7f
#define BINS    65536           // scores < 1.0 => (bits>>14) <= 65024
#define BIN_SHIFT 14
#define SORTN   8192
#define NPAD    6016            // 94 * 64
#define NPAD2   (NPAD + 40)     // prefetch overrun padding
#define NWORDS  94
#define RC4N    24              // ceil(94/4)

typedef unsigned long long u64;
typedef unsigned int u32;

// ---------------- static device scratch ----------------
__device__ u32 g_hist[BATCH * BINS];             // 2 MB
__device__ u64 g_main[BATCH * TOPK];
__device__ u64 g_bnd[BATCH * NELEM];
__device__ u32 g_cnt_main[BATCH];
__device__ u32 g_cnt_bnd[BATCH];
__device__ u32 g_pbin[BATCH];

__device__ float4 g_sbox[BATCH][NPAD];           // sorted, decoded, clipped boxes
__device__ float  g_area[BATCH][NPAD];
__device__ u64    g_mask[BATCH][NPAD2][NWORDS];  // suppression bitmasks (upper tri valid)

// ---------------- kernel 0: zero scratch (vectorized) ----------------
__global__ void k_zero(){
    u32 i = blockIdx.x * blockDim.x + threadIdx.x;        // over uint4 groups
    ((uint4*)g_hist)[i] = make_uint4(0u, 0u, 0u, 0u);
    if (i < BATCH) { g_cnt_main[i] = 0; g_cnt_bnd[i] = 0; }
}

// ---------------- kernel 1: histogram (4 elems/thread) ----------------
__global__ void k_hist(const float4* __restrict__ cls4) {
    u32 i = blockIdx.x * blockDim.x + threadIdx.x;   // group of 4 elements
    float4 p0 = cls4[2 * i];
    float4 p1 = cls4[2 * i + 1];
    u32 b = (i << 2) >> NSHIFT;                      // all 4 in same batch
    u32* h = &g_hist[b * BINS];
    u32 b0 = min(__float_as_uint(p0.y) >> BIN_SHIFT, (u32)(BINS - 1));
    u32 b1 = min(__float_as_uint(p0.w) >> BIN_SHIFT, (u32)(BINS - 1));
    u32 b2 = min(__float_as_uint(p1.y) >> BIN_SHIFT, (u32)(BINS - 1));
    u32 b3 = min(__float_as_uint(p1.w) >> BIN_SHIFT, (u32)(BINS - 1));
    atomicAdd(&h[b0], 1u);
    atomicAdd(&h[b1], 1u);
    atomicAdd(&h[b2], 1u);
    atomicAdd(&h[b3], 1u);
}

// ---------------- kernel 2: find per-batch threshold bin ----------------
__global__ void __launch_bounds__(1024) k_select() {
    int b = blockIdx.x;
    int tid = threadIdx.x;
    const int CH = BINS / 1024;                  // 64 bins per thread
    const u32* hist = &g_hist[b * BINS];

    u32 mysum = 0;
    int base = tid * CH;
    #pragma unroll 8
    for (int k = 0; k < CH; k++) mysum += hist[base + k];

    __shared__ u32 ss[1024];
    ss[tid] = mysum;
    __syncthreads();
    for (int off = 1; off < 1024; off <<= 1) {
        u32 v = (tid + off < 1024) ? ss[tid + off] : 0u;
        __syncthreads();
        ss[tid] += v;
        __syncthreads();
    }
    u32 A = ss[tid] - mysum;                     // strictly-above count
    if (A < TOPK && A + mysum >= TOPK) {
        u32 acc = A;
        for (int bin = base + CH - 1; bin >= base; --bin) {
            u32 h = hist[bin];
            if (acc + h >= TOPK) { g_pbin[b] = (u32)bin; break; }
            acc += h;
        }
    }
}

// ---------------- kernel 3: compaction (4 elems/thread) ----------------
__global__ void k_compact(const float4* __restrict__ cls4) {
    u32 i = blockIdx.x * blockDim.x + threadIdx.x;   // group of 4 elements
    float4 p0 = cls4[2 * i];
    float4 p1 = cls4[2 * i + 1];
    u32 base = i << 2;
    u32 b = base >> NSHIFT;
    u32 p = g_pbin[b];
    float sc[4] = {p0.y, p0.w, p1.y, p1.w};
    #pragma unroll
    for (int k = 0; k < 4; k++) {
        u32 bits = __float_as_uint(sc[k]);
        u32 bin = min(bits >> BIN_SHIFT, (u32)(BINS - 1));
        u32 idx = (base + k) & (NELEM - 1);
        if (bin > p) {
            u32 pos = atomicAdd(&g_cnt_main[b], 1u);
            g_main[b * TOPK + pos] = ((u64)bits << 32) | (u32)(~idx);
        } else if (bin == p) {
            u32 pos = atomicAdd(&g_cnt_bnd[b], 1u);
            g_bnd[(u32)b * NELEM + pos] = ((u64)bits << 32) | (u32)(~idx);
        }
    }
}

// ---------------- kernel 4: sort keys, decode boxes -> global ----------------
__global__ void __launch_bounds__(1024, 1)
k_sort(const float4* __restrict__ bbox, const float4* __restrict__ anchors) {
    extern __shared__ __align__(16) unsigned char smem_raw[];
    u64* keys = (u64*)smem_raw;                  // 8192 * 8 = 65536

    int b = blockIdx.x;
    int tid = threadIdx.x;
    int lane = tid & 31;
    int wid = tid >> 5;

    u32 cnt_main = g_cnt_main[b];
    u32 m = g_cnt_bnd[b];
    u32 total = cnt_main + m;

    for (u32 i = tid; i < cnt_main; i += 1024) keys[i] = g_main[b * TOPK + i];

    if (total <= SORTN) {
        for (u32 i = tid; i < m; i += 1024) keys[cnt_main + i] = g_bnd[(u32)b * NELEM + i];
        for (u32 i = total + tid; i < SORTN; i += 1024) keys[i] = 0ull;
        __syncthreads();
    } else {
        // pathological fallback: iteratively select top-r boundary keys
        for (u32 i = cnt_main + tid; i < SORTN; i += 1024) keys[i] = 0ull;
        __syncthreads();
        __shared__ u64 rk[32];
        __shared__ u32 rp[32];
        int r = TOPK - (int)cnt_main;
        for (int round = 0; round < r; ++round) {
            u64 bk = 0; u32 bp = 0;
            for (u32 i = tid; i < m; i += 1024) {
                u64 v = g_bnd[(u32)b * NELEM + i];
                if (v > bk) { bk = v; bp = i; }
            }
            for (int off = 16; off; off >>= 1) {
                u64 ok = __shfl_down_sync(0xFFFFFFFFu, bk, off);
                u32 op = __shfl_down_sync(0xFFFFFFFFu, bp, off);
                if (ok > bk) { bk = ok; bp = op; }
            }
            if (lane == 0) { rk[wid] = bk; rp[wid] = bp; }
            __syncthreads();
            if (wid == 0) {
                bk = rk[lane]; bp = rp[lane];
                for (int off = 16; off; off >>= 1) {
                    u64 ok = __shfl_down_sync(0xFFFFFFFFu, bk, off);
                    u32 op = __shfl_down_sync(0xFFFFFFFFu, bp, off);
                    if (ok > bk) { bk = ok; bp = op; }
                }
                if (lane == 0) {
                    keys[cnt_main + round] = bk;
                    g_bnd[(u32)b * NELEM + bp] = 0ull;
                }
            }
            __syncthreads();
        }
    }

    // bitonic sort descending
    for (u32 k = 2; k <= SORTN; k <<= 1) {
        for (u32 j = k >> 1; j; j >>= 1) {
            for (u32 i = tid; i < SORTN; i += 1024) {
                u32 ix = i ^ j;
                if (ix > i) {
                    u64 a = keys[i], c = keys[ix];
                    bool dirDesc = ((i & k) == 0);
                    if ((a < c) == dirDesc) { keys[i] = c; keys[ix] = a; }
                }
            }
            __syncthreads();
        }
    }

    // decode boxes for top slots, write to global (+ zero pad)
    for (int s = tid; s < NPAD; s += 1024) {
        if (s < TOPK) {
            u64 key = keys[s];
            u32 idx = ~(u32)(key & 0xFFFFFFFFull);
            u32 gi = ((u32)b << NSHIFT) + idx;
            float4 a = anchors[gi];
            float4 d = bbox[gi];
            d.x *= 0.1f; d.y *= 0.1f; d.z *= 0.2f; d.w *= 0.2f;
            float h = a.z - a.x;
            float w = a.w - a.y;
            float cy = a.x + 0.5f * h;
            float cx = a.y + 0.5f * w;
            cy = cy + d.x * h;
            cx = cx + d.y * w;
            h = h * expf(d.z);
            w = w * expf(d.w);
            float4 box;
            box.x = fminf(fmaxf(cy - 0.5f * h, 0.0f), 1.0f);
            box.y = fminf(fmaxf(cx - 0.5f * w, 0.0f), 1.0f);
            box.z = fminf(fmaxf(cy + 0.5f * h, 0.0f), 1.0f);
            box.w = fminf(fmaxf(cx + 0.5f * w, 0.0f), 1.0f);
            g_sbox[b][s] = box;
            g_area[b][s] = (box.z - box.x) * (box.w - box.y);
        } else {
            g_sbox[b][s] = make_float4(0.0f, 0.0f, 0.0f, 0.0f);
            g_area[b][s] = 0.0f;
        }
    }
}

// ---------------- kernel 5: pairwise IoU suppression bitmask ----------------
// Triangular grid; division-free fast path with exact near-threshold fixup.
__constant__ u32 c_tri[RC4N];    // prefix of live (rc4 -> first flat index)

__global__ void __launch_bounds__(256) k_mask() {
    // decode flat triangular index -> (rc4, cc)
    u32 flat = blockIdx.x;
    int rc4 = 0;
    #pragma unroll
    for (int k = 0; k < RC4N; k++) if (flat >= c_tri[k]) rc4 = k;
    int cc = (rc4 << 2) + (int)(flat - c_tri[rc4]);
    int b = blockIdx.z;

    __shared__ float4 cbox[64];
    __shared__ float  ca07[64];      // 0.7 * area
    __shared__ float  ca[64];        // exact area (fallback path)
    int t = threadIdx.x;
    int col0 = cc << 6;
    if (t < 64) {
        cbox[t] = g_sbox[b][col0 + t];
        float ar = g_area[b][col0 + t];
        ca[t] = ar;
        ca07[t] = 0.7f * ar;
    }
    __syncthreads();

    int rc = (rc4 << 2) + (t >> 6);
    if (rc > cc || rc >= NWORDS) return;
    int i = (rc << 6) + (t & 63);
    float4 a = g_sbox[b][i];
    float areaA = g_area[b][i];
    float a07 = 0.7f * areaA;

    u64 bits = 0, nearb = 0;
    if (cc != rc) {
        // off-diagonal: all 64 columns are strictly after row i
        #pragma unroll 16
        for (int j = 0; j < 64; j++) {
            float4 c = cbox[j];
            float y1 = fmaxf(a.x, c.x);
            float x1 = fmaxf(a.y, c.y);
            float y2 = fminf(a.z, c.z);
            float x2 = fminf(a.w, c.w);
            float inter = fmaxf(y2 - y1, 0.0f) * fmaxf(x2 - x1, 0.0f);
            float rhs = a07 + ca07[j];
            float d = fmaf(1.7f, inter, -rhs);
            float mg = fmaf(1e-4f, rhs, 1e-12f);
            if (d > 0.0f) bits |= (1ull << j);
            if (fabsf(d) < mg) nearb |= (1ull << j);
        }
    } else {
        #pragma unroll 16
        for (int j = 0; j < 64; j++) {
            if (col0 + j > i) {
                float4 c = cbox[j];
                float y1 = fmaxf(a.x, c.x);
                float x1 = fmaxf(a.y, c.y);
                float y2 = fminf(a.z, c.z);
                float x2 = fminf(a.w, c.w);
                float inter = fmaxf(y2 - y1, 0.0f) * fmaxf(x2 - x1, 0.0f);
                float rhs = a07 + ca07[j];
                float d = fmaf(1.7f, inter, -rhs);
                float mg = fmaf(1e-4f, rhs, 1e-12f);
                if (d > 0.0f) bits |= (1ull << j);
                if (fabsf(d) < mg) nearb |= (1ull << j);
            }
        }
    }

    // rare exact fixup (reference rounding order, IEEE div)
    while (nearb) {
        int j = __ffsll((long long)nearb) - 1;
        nearb &= nearb - 1;
        float4 c = cbox[j];
        float y1 = fmaxf(a.x, c.x);
        float x1 = fmaxf(a.y, c.y);
        float y2 = fminf(a.z, c.z);
        float x2 = fminf(a.w, c.w);
        float inter = fmaxf(y2 - y1, 0.0f) * fmaxf(x2 - x1, 0.0f);
        float denom = areaA + ca[j] - inter + 1e-9f;
        float iou = inter / denom;
        if (iou > NMS_THR) bits |= (1ull << j);
        else               bits &= ~(1ull << j);
    }

    g_mask[b][i][cc] = bits;
}

// ---------------- kernel 6: serial greedy pass over bitmasks ----------------
// Per-selection critical path is register/shfl only:
//   ffs -> shfl(diag word) -> AND -> ffs.
// Suppression-set lives in 3 registers per lane; selected rows fold lazily
// at word transitions with 4-way MLP (rows prefetched at selection time).
__global__ void __launch_bounds__(32) k_seq(float4* __restrict__ out) {
    int b = blockIdx.x;
    int lane = threadIdx.x;

    __shared__ int ssel[64];

    const float4* sb = g_sbox[b];
    float4* ob = out + b * NOUT;

    u64 r0 = 0, r1 = 0, r2 = 0;      // remv words: lane, lane+32, lane+64
    const int j1 = lane, j2 = lane + 32, j3 = lane + 64;
    const bool g3 = (j3 < NWORDS);
    int cnt = 0;

    // prefetch word 0 diagonal gather
    {
        const char* p0 = (const char*)&g_mask[b][lane][0];
        const char* p1 = (const char*)&g_mask[b][32 + lane][0];
        asm volatile("prefetch.global.L1 [%0];" :: "l"(p0));
        asm volatile("prefetch.global.L1 [%0];" :: "l"(p1));
    }

    for (int w = 0; w < NWORDS && cnt < NOUT; w++) {
        // remv[w] via shfl from the owning lane/register
        u64 rv;
        if (w < 32)      rv = __shfl_sync(0xFFFFFFFFu, r0, w);
        else if (w < 64) rv = __shfl_sync(0xFFFFFFFFu, r1, w - 32);
        else             rv = __shfl_sync(0xFFFFFFFFu, r2, w - 64);

        u64 live = (w == NWORDS - 1) ? ((1ull << 48) - 1ull) : ~0ull;
        u64 rw = (~rv) & live;

        // prefetch next word's diagonal gather
        if (w + 1 < NWORDS) {
            const char* p0 = (const char*)&g_mask[b][((w + 1) << 6) + lane][w + 1];
            const char* p1 = (const char*)&g_mask[b][((w + 1) << 6) + 32 + lane][w + 1];
            asm volatile("prefetch.global.L1 [%0];" :: "l"(p0));
            asm volatile("prefetch.global.L1 [%0];" :: "l"(p1));
        }
        if (!rw) continue;

        // gather diagonal words for all 64 candidates of this word
        u64 m0 = g_mask[b][(w << 6) + lane][w];
        u64 m1 = g_mask[b][(w << 6) + 32 + lane][w];

        int nsel = 0;
        while (rw && cnt < NOUT) {
            int bit = __ffsll((long long)rw) - 1;
            int i = (w << 6) + bit;

            if (lane == 0) { ob[cnt] = sb[i]; ssel[nsel] = i; }
            cnt++; nsel++;

            // prefetch row i for the lazy fold (94 words = 6 lines)
            if (lane < 6) {
                const char* p = (const char*)&g_mask[b][i][0] + (u32)lane * 128;
                asm volatile("prefetch.global.L1 [%0];" :: "l"(p));
            }

            // critical path: shfl-broadcast of i's diagonal word
            u64 mw = (bit < 32) ? __shfl_sync(0xFFFFFFFFu, m0, bit)
                                : __shfl_sync(0xFFFFFFFFu, m1, bit - 32);
            rw &= ~mw;
            rw &= ~(1ull << bit);
        }
        __syncwarp();

        // lazy fold of selected rows into register remv, 4-way MLP
        int k = 0;
        for (; k + 4 <= nsel; k += 4) {
            const u64* p0 = &g_mask[b][ssel[k]][0];
            const u64* p1 = &g_mask[b][ssel[k + 1]][0];
            const u64* p2 = &g_mask[b][ssel[k + 2]][0];
            const u64* p3 = &g_mask[b][ssel[k + 3]][0];
            u64 a0 = p0[j1], a1 = p1[j1], a2 = p2[j1], a3 = p3[j1];
            u64 b0 = p0[j2], b1 = p1[j2], b2 = p2[j2], b3 = p3[j2];
            u64 c0 = 0, c1 = 0, c2 = 0, c3 = 0;
            if (g3) { c0 = p0[j3]; c1 = p1[j3]; c2 = p2[j3]; c3 = p3[j3]; }
            r0 |= a0 | a1 | a2 | a3;
            r1 |= b0 | b1 | b2 | b3;
            r2 |= c0 | c1 | c2 | c3;
        }
        for (; k < nsel; k++) {
            const u64* p0 = &g_mask[b][ssel[k]][0];
            r0 |= p0[j1];
            r1 |= p0[j2];
            if (g3) r2 |= p0[j3];
        }
        __syncwarp();
    }

    for (int q = cnt + lane; q < NOUT; q += 32)
        ob[q] = make_float4(0.0f, 0.0f, 0.0f, 0.0f);
}

// ---------------- launch ----------------
extern "C" void kernel_launch(void* const* d_in, const int* in_sizes, int n_in,
                              void* d_out, int out_size) {
    const float4* cls4    = (const float4*)d_in[0];
    const float4* bbox    = (const float4*)d_in[1];
    const float4* anchors = (const float4*)d_in[2];
    float4* out = (float4*)d_out;

    (void)in_sizes; (void)n_in; (void)out_size;

    const int total = BATCH * NELEM;

    // triangular block index prefix (constant, value-identical every call)
    static bool tri_done = false;
    static u32 tri[RC4N];
    static u32 tri_total = 0;
    if (!tri_done) {
        u32 acc = 0;
        for (int r = 0; r < RC4N; r++) {
            tri[r] = acc;
            acc += (u32)(NWORDS - (r << 2));   // cc in [4r, 93]
        }
        tri_total = acc;
        tri_done = true;
    }
    cudaMemcpyToSymbolAsync(c_tri, tri, sizeof(tri), 0, cudaMemcpyHostToDevice);

    k_zero<<<(BATCH * BINS / 4) / 256, 256>>>();
    k_hist<<<(total / 4) / 256, 256>>>(cls4);
    k_select<<<BATCH, 1024>>>();
    k_compact<<<(total / 4) / 256, 256>>>(cls4);

    cudaFuncSetAttribute(k_sort, cudaFuncAttributeMaxDynamicSharedMemorySize, 65536);
    k_sort<<<BATCH, 1024, 65536>>>(bbox, anchors);

    dim3 mgrid(tri_total, 1, BATCH);
    k_mask<<<mgrid, 256>>>();

    k_seq<<<BATCH, 32>>>(out);
}

// round 12
// speedup vs baseline: 1.2722x; 1.0406x over previous
#include <cuda_runtime.h>
#include <cuda_bf16.h>
#include <cstdint>

// Problem constants
#define BATCH   8
#define NELEM   262144          // 2^18
#define NSHIFT  18
#define TOPK    6000
#define NOUT    1000
#define NMS_THR 0.7f
#define BINS    65536           // scores < 1.0 => (bits>>14) <= 65024
#define BIN_SHIFT 14
#define SORTN   8192
#define NPAD    6016            // 94 * 64
#define NPAD2   (NPAD + 40)     // prefetch overrun padding
#define NWORDS  94
#define RC4N    24              // ceil(94/4)
#define TRI_TOTAL 1152

typedef unsigned long long u64;
typedef unsigned int u32;

// ---------------- static device scratch ----------------
__device__ u32 g_hist[BATCH * BINS];             // 2 MB
__device__ u64 g_main[BATCH * TOPK];
__device__ u64 g_bnd[BATCH * NELEM];
__device__ u32 g_cnt_main[BATCH];
__device__ u32 g_cnt_bnd[BATCH];
__device__ u32 g_pbin[BATCH];

__device__ float4 g_sbox[BATCH][NPAD];           // sorted, decoded, clipped boxes
__device__ float  g_area[BATCH][NPAD];
__device__ u64    g_mask[BATCH][NPAD2][NWORDS];  // suppression bitmasks (upper tri valid)

// triangular grid prefix: tri[r] = 94r - 2r(r-1) (compile-time)
__constant__ u32 c_tri[RC4N] = {
    0, 94, 184, 270, 352, 430, 504, 574, 640, 702, 760, 814,
    864, 910, 952, 990, 1024, 1054, 1080, 1102, 1120, 1134, 1144, 1150
};

// ---------------- kernel 0: zero scratch (vectorized) ----------------
__global__ void k_zero(){
    u32 i = blockIdx.x * blockDim.x + threadIdx.x;        // over uint4 groups
    ((uint4*)g_hist)[i] = make_uint4(0u, 0u, 0u, 0u);
    if (i < BATCH) { g_cnt_main[i] = 0; g_cnt_bnd[i] = 0; }
}

// ---------------- kernel 1: histogram (4 elems/thread) ----------------
__global__ void k_hist(const float4* __restrict__ cls4) {
    u32 i = blockIdx.x * blockDim.x + threadIdx.x;   // group of 4 elements
    float4 p0 = cls4[2 * i];
    float4 p1 = cls4[2 * i + 1];
    u32 b = (i << 2) >> NSHIFT;                      // all 4 in same batch
    u32* h = &g_hist[b * BINS];
    u32 b0 = min(__float_as_uint(p0.y) >> BIN_SHIFT, (u32)(BINS - 1));
    u32 b1 = min(__float_as_uint(p0.w) >> BIN_SHIFT, (u32)(BINS - 1));
    u32 b2 = min(__float_as_uint(p1.y) >> BIN_SHIFT, (u32)(BINS - 1));
    u32 b3 = min(__float_as_uint(p1.w) >> BIN_SHIFT, (u32)(BINS - 1));
    atomicAdd(&h[b0], 1u);
    atomicAdd(&h[b1], 1u);
    atomicAdd(&h[b2], 1u);
    atomicAdd(&h[b3], 1u);
}

// ---------------- kernel 2: find per-batch threshold bin ----------------
__global__ void __launch_bounds__(1024) k_select() {
    int b = blockIdx.x;
    int tid = threadIdx.x;
    const int CH = BINS / 1024;                  // 64 bins per thread
    const u32* hist = &g_hist[b * BINS];

    u32 mysum = 0;
    int base = tid * CH;
    #pragma unroll 8
    for (int k = 0; k < CH; k++) mysum += hist[base + k];

    __shared__ u32 ss[1024];
    ss[tid] = mysum;
    __syncthreads();
    for (int off = 1; off < 1024; off <<= 1) {
        u32 v = (tid + off < 1024) ? ss[tid + off] : 0u;
        __syncthreads();
        ss[tid] += v;
        __syncthreads();
    }
    u32 A = ss[tid] - mysum;                     // strictly-above count
    if (A < TOPK && A + mysum >= TOPK) {
        u32 acc = A;
        for (int bin = base + CH - 1; bin >= base; --bin) {
            u32 h = hist[bin];
            if (acc + h >= TOPK) { g_pbin[b] = (u32)bin; break; }
            acc += h;
        }
    }
}

// ---------------- kernel 3: compaction (4 elems/thread) ----------------
__global__ void k_compact(const float4* __restrict__ cls4) {
    u32 i = blockIdx.x * blockDim.x + threadIdx.x;   // group of 4 elements
    float4 p0 = cls4[2 * i];
    float4 p1 = cls4[2 * i + 1];
    u32 base = i << 2;
    u32 b = base >> NSHIFT;
    u32 p = g_pbin[b];
    float sc[4] = {p0.y, p0.w, p1.y, p1.w};
    #pragma unroll
    for (int k = 0; k < 4; k++) {
        u32 bits = __float_as_uint(sc[k]);
        u32 bin = min(bits >> BIN_SHIFT, (u32)(BINS - 1));
        u32 idx = (base + k) & (NELEM - 1);
        if (bin > p) {
            u32 pos = atomicAdd(&g_cnt_main[b], 1u);
            g_main[b * TOPK + pos] = ((u64)bits << 32) | (u32)(~idx);
        } else if (bin == p) {
            u32 pos = atomicAdd(&g_cnt_bnd[b], 1u);
            g_bnd[(u32)b * NELEM + pos] = ((u64)bits << 32) | (u32)(~idx);
        }
    }
}

// ---------------- kernel 4: sort keys, decode boxes -> global ----------------
// One bitonic compare-exchange micro-step on 8 register-resident elements.
__device__ __forceinline__ void reg_step(u64* e, int base, int k, int j) {
    #pragma unroll
    for (int a = 0; a < 8; a++) {
        if ((a & j) == 0) {
            int p = a | j;
            bool dirDesc = (((base + a) & k) == 0);
            u64 x = e[a], y = e[p];
            if ((x < y) == dirDesc) { e[a] = y; e[p] = x; }
        }
    }
}

__global__ void __launch_bounds__(1024, 1)
k_sort(const float4* __restrict__ bbox, const float4* __restrict__ anchors) {
    extern __shared__ __align__(16) unsigned char smem_raw[];
    u64* keys = (u64*)smem_raw;                  // 8192 * 8 = 65536

    int b = blockIdx.x;
    int tid = threadIdx.x;
    int lane = tid & 31;
    int wid = tid >> 5;

    u32 cnt_main = g_cnt_main[b];
    u32 m = g_cnt_bnd[b];
    u32 total = cnt_main + m;

    for (u32 i = tid; i < cnt_main; i += 1024) keys[i] = g_main[b * TOPK + i];

    if (total <= SORTN) {
        for (u32 i = tid; i < m; i += 1024) keys[cnt_main + i] = g_bnd[(u32)b * NELEM + i];
        for (u32 i = total + tid; i < SORTN; i += 1024) keys[i] = 0ull;
        __syncthreads();
    } else {
        // pathological fallback: iteratively select top-r boundary keys
        for (u32 i = cnt_main + tid; i < SORTN; i += 1024) keys[i] = 0ull;
        __syncthreads();
        __shared__ u64 rk[32];
        __shared__ u32 rp[32];
        int r = TOPK - (int)cnt_main;
        for (int round = 0; round < r; ++round) {
            u64 bk = 0; u32 bp = 0;
            for (u32 i = tid; i < m; i += 1024) {
                u64 v = g_bnd[(u32)b * NELEM + i];
                if (v > bk) { bk = v; bp = i; }
            }
            for (int off = 16; off; off >>= 1) {
                u64 ok = __shfl_down_sync(0xFFFFFFFFu, bk, off);
                u32 op = __shfl_down_sync(0xFFFFFFFFu, bp, off);
                if (ok > bk) { bk = ok; bp = op; }
            }
            if (lane == 0) { rk[wid] = bk; rp[wid] = bp; }
            __syncthreads();
            if (wid == 0) {
                bk = rk[lane]; bp = rp[lane];
                for (int off = 16; off; off >>= 1) {
                    u64 ok = __shfl_down_sync(0xFFFFFFFFu, bk, off);
                    u32 op = __shfl_down_sync(0xFFFFFFFFu, bp, off);
                    if (ok > bk) { bk = ok; bp = op; }
                }
                if (lane == 0) {
                    keys[cnt_main + round] = bk;
                    g_bnd[(u32)b * NELEM + bp] = 0ull;
                }
            }
            __syncthreads();
        }
    }

    // -------- register-blocked bitonic sort (descending) --------
    int rbase = tid * 8;
    u64 e[8];
    {
        // prologue: stages k=2,4,8 entirely in registers
        ulonglong2* kv = reinterpret_cast<ulonglong2*>(keys + rbase);
        ulonglong2 v0 = kv[0], v1 = kv[1], v2 = kv[2], v3 = kv[3];
        e[0]=v0.x; e[1]=v0.y; e[2]=v1.x; e[3]=v1.y;
        e[4]=v2.x; e[5]=v2.y; e[6]=v3.x; e[7]=v3.y;
        reg_step(e, rbase, 2, 1);
        reg_step(e, rbase, 4, 2); reg_step(e, rbase, 4, 1);
        reg_step(e, rbase, 8, 4); reg_step(e, rbase, 8, 2); reg_step(e, rbase, 8, 1);
        kv[0] = make_ulonglong2(e[0], e[1]);
        kv[1] = make_ulonglong2(e[2], e[3]);
        kv[2] = make_ulonglong2(e[4], e[5]);
        kv[3] = make_ulonglong2(e[6], e[7]);
    }
    __syncthreads();

    for (u32 k = 16; k <= SORTN; k <<= 1) {
        for (u32 j = k >> 1; j >= 8; j >>= 1) {
            for (u32 i = tid; i < SORTN; i += 1024) {
                u32 ix = i ^ j;
                if (ix > i) {
                    u64 a = keys[i], c = keys[ix];
                    bool dirDesc = ((i & k) == 0);
                    if ((a < c) == dirDesc) { keys[i] = c; keys[ix] = a; }
                }
            }
            __syncthreads();
        }
        // j = 4,2,1 in registers
        {
            ulonglong2* kv = reinterpret_cast<ulonglong2*>(keys + rbase);
            ulonglong2 v0 = kv[0], v1 = kv[1], v2 = kv[2], v3 = kv[3];
            e[0]=v0.x; e[1]=v0.y; e[2]=v1.x; e[3]=v1.y;
            e[4]=v2.x; e[5]=v2.y; e[6]=v3.x; e[7]=v3.y;
            reg_step(e, rbase, (int)k, 4);
            reg_step(e, rbase, (int)k, 2);
            reg_step(e, rbase, (int)k, 1);
            kv[0] = make_ulonglong2(e[0], e[1]);
            kv[1] = make_ulonglong2(e[2], e[3]);
            kv[2] = make_ulonglong2(e[4], e[5]);
            kv[3] = make_ulonglong2(e[6], e[7]);
        }
        __syncthreads();
    }

    // decode boxes for top slots, write to global (+ zero pad)
    for (int s = tid; s < NPAD; s += 1024) {
        if (s < TOPK) {
            u64 key = keys[s];
            u32 idx = ~(u32)(key & 0xFFFFFFFFull);
            u32 gi = ((u32)b << NSHIFT) + idx;
            float4 a = anchors[gi];
            float4 d = bbox[gi];
            d.x *= 0.1f; d.y *= 0.1f; d.z *= 0.2f; d.w *= 0.2f;
            float h = a.z - a.x;
            float w = a.w - a.y;
            float cy = a.x + 0.5f * h;
            float cx = a.y + 0.5f * w;
            cy = cy + d.x * h;
            cx = cx + d.y * w;
            h = h * expf(d.z);
            w = w * expf(d.w);
            float4 box;
            box.x = fminf(fmaxf(cy - 0.5f * h, 0.0f), 1.0f);
            box.y = fminf(fmaxf(cx - 0.5f * w, 0.0f), 1.0f);
            box.z = fminf(fmaxf(cy + 0.5f * h, 0.0f), 1.0f);
            box.w = fminf(fmaxf(cx + 0.5f * w, 0.0f), 1.0f);
            g_sbox[b][s] = box;
            g_area[b][s] = (box.z - box.x) * (box.w - box.y);
        } else {
            g_sbox[b][s] = make_float4(0.0f, 0.0f, 0.0f, 0.0f);
            g_area[b][s] = 0.0f;
        }
    }
}

// ---------------- kernel 5: pairwise IoU suppression bitmask ----------------
// Triangular grid; division-free fast path with exact near-threshold fixup.
__global__ void __launch_bounds__(256) k_mask() {
    // decode flat triangular index -> (rc4, cc)
    u32 flat = blockIdx.x;
    int rc4 = 0;
    #pragma unroll
    for (int k = 0; k < RC4N; k++) if (flat >= c_tri[k]) rc4 = k;
    int cc = (rc4 << 2) + (int)(flat - c_tri[rc4]);
    int b = blockIdx.z;

    __shared__ float4 cbox[64];
    __shared__ float  ca07[64];      // 0.7 * area
    __shared__ float  ca[64];        // exact area (fallback path)
    int t = threadIdx.x;
    int col0 = cc << 6;
    if (t < 64) {
        cbox[t] = g_sbox[b][col0 + t];
        float ar = g_area[b][col0 + t];
        ca[t] = ar;
        ca07[t] = 0.7f * ar;
    }
    __syncthreads();

    int rc = (rc4 << 2) + (t >> 6);
    if (rc > cc || rc >= NWORDS) return;
    int i = (rc << 6) + (t & 63);
    float4 a = g_sbox[b][i];
    float areaA = g_area[b][i];
    float a07 = 0.7f * areaA;

    u64 bits = 0, nearb = 0;
    if (cc != rc) {
        // off-diagonal: all 64 columns are strictly after row i
        #pragma unroll 16
        for (int j = 0; j < 64; j++) {
            float4 c = cbox[j];
            float y1 = fmaxf(a.x, c.x);
            float x1 = fmaxf(a.y, c.y);
            float y2 = fminf(a.z, c.z);
            float x2 = fminf(a.w, c.w);
            float inter = fmaxf(y2 - y1, 0.0f) * fmaxf(x2 - x1, 0.0f);
            float rhs = a07 + ca07[j];
            float d = fmaf(1.7f, inter, -rhs);
            float mg = fmaf(1e-4f, rhs, 1e-12f);
            if (d > 0.0f) bits |= (1ull << j);
            if (fabsf(d) < mg) nearb |= (1ull << j);
        }
    } else {
        #pragma unroll 16
        for (int j = 0; j < 64; j++) {
            if (col0 + j > i) {
                float4 c = cbox[j];
                float y1 = fmaxf(a.x, c.x);
                float x1 = fmaxf(a.y, c.y);
                float y2 = fminf(a.z, c.z);
                float x2 = fminf(a.w, c.w);
                float inter = fmaxf(y2 - y1, 0.0f) * fmaxf(x2 - x1, 0.0f);
                float rhs = a07 + ca07[j];
                float d = fmaf(1.7f, inter, -rhs);
                float mg = fmaf(1e-4f, rhs, 1e-12f);
                if (d > 0.0f) bits |= (1ull << j);
                if (fabsf(d) < mg) nearb |= (1ull << j);
            }
        }
    }

    // rare exact fixup (reference rounding order, IEEE div)
    while (nearb) {
        int j = __ffsll((long long)nearb) - 1;
        nearb &= nearb - 1;
        float4 c = cbox[j];
        float y1 = fmaxf(a.x, c.x);
        float x1 = fmaxf(a.y, c.y);
        float y2 = fminf(a.z, c.z);
        float x2 = fminf(a.w, c.w);
        float inter = fmaxf(y2 - y1, 0.0f) * fmaxf(x2 - x1, 0.0f);
        float denom = areaA + ca[j] - inter + 1e-9f;
        float iou = inter / denom;
        if (iou > NMS_THR) bits |= (1ull << j);
        else               bits &= ~(1ull << j);
    }

    g_mask[b][i][cc] = bits;
}

// ---------------- kernel 6: serial greedy pass over bitmasks ----------------
// Per-selection critical path is register/shfl only. At each word entry the
// 64-lane diagonal gather is ISSUED first, then the previous word's selected
// rows (L1-prefetched) are folded while the gather is in flight.
__global__ void __launch_bounds__(32) k_seq(float4* __restrict__ out) {
    int b = blockIdx.x;
    int lane = threadIdx.x;

    __shared__ int ssel[64];

    const float4* sb = g_sbox[b];
    float4* ob = out + b * NOUT;

    u64 r0 = 0, r1 = 0, r2 = 0;      // remv words: lane, lane+32, lane+64
    const int j1 = lane, j2 = lane + 32, j3 = lane + 64;
    const bool g3 = (j3 < NWORDS);
    int cnt = 0;
    int npend = 0;                   // selections pending fold

    // prefetch word 0 diagonal gather
    {
        const char* p0 = (const char*)&g_mask[b][lane][0];
        const char* p1 = (const char*)&g_mask[b][32 + lane][0];
        asm volatile("prefetch.global.L1 [%0];" :: "l"(p0));
        asm volatile("prefetch.global.L1 [%0];" :: "l"(p1));
    }

    for (int w = 0; w < NWORDS && cnt < NOUT; w++) {
        // 1) issue this word's diagonal gather (consumed after the fold)
        u64 m0 = g_mask[b][(w << 6) + lane][w];
        u64 m1 = g_mask[b][(w << 6) + 32 + lane][w];

        // 2) fold pending rows from the previous word (L1-prefetched), 4-way MLP
        int k = 0;
        for (; k + 4 <= npend; k += 4) {
            const u64* p0 = &g_mask[b][ssel[k]][0];
            const u64* p1 = &g_mask[b][ssel[k + 1]][0];
            const u64* p2 = &g_mask[b][ssel[k + 2]][0];
            const u64* p3 = &g_mask[b][ssel[k + 3]][0];
            u64 a0 = p0[j1], a1 = p1[j1], a2 = p2[j1], a3 = p3[j1];
            u64 b0 = p0[j2], b1 = p1[j2], b2 = p2[j2], b3 = p3[j2];
            u64 c0 = 0, c1 = 0, c2 = 0, c3 = 0;
            if (g3) { c0 = p0[j3]; c1 = p1[j3]; c2 = p2[j3]; c3 = p3[j3]; }
            r0 |= a0 | a1 | a2 | a3;
            r1 |= b0 | b1 | b2 | b3;
            r2 |= c0 | c1 | c2 | c3;
        }
        for (; k < npend; k++) {
            const u64* p0 = &g_mask[b][ssel[k]][0];
            r0 |= p0[j1];
            r1 |= p0[j2];
            if (g3) r2 |= p0[j3];
        }
        npend = 0;

        // 3) remaining-candidates word from register remv
        u64 rv;
        if (w < 32)      rv = __shfl_sync(0xFFFFFFFFu, r0, w);
        else if (w < 64) rv = __shfl_sync(0xFFFFFFFFu, r1, w - 32);
        else             rv = __shfl_sync(0xFFFFFFFFu, r2, w - 64);
        u64 live = (w == NWORDS - 1) ? ((1ull << 48) - 1ull) : ~0ull;
        u64 rw = (~rv) & live;

        // 4) prefetch next word's diagonal gather
        if (w + 1 < NWORDS) {
            const char* p0 = (const char*)&g_mask[b][((w + 1) << 6) + lane][w + 1];
            const char* p1 = (const char*)&g_mask[b][((w + 1) << 6) + 32 + lane][w + 1];
            asm volatile("prefetch.global.L1 [%0];" :: "l"(p0));
            asm volatile("prefetch.global.L1 [%0];" :: "l"(p1));
        }
        if (!rw) continue;

        // 5) selection loop: shfl-only critical path
        while (rw && cnt < NOUT) {
            int bit = __ffsll((long long)rw) - 1;
            int i = (w << 6) + bit;

            if (lane == 0) { ob[cnt] = sb[i]; ssel[npend] = i; }
            cnt++; npend++;

            // prefetch row i for the next word's fold (94 words = 6 lines)
            if (lane < 6) {
                const char* p = (const char*)&g_mask[b][i][0] + (u32)lane * 128;
                asm volatile("prefetch.global.L1 [%0];" :: "l"(p));
            }

            u64 mw = (bit < 32) ? __shfl_sync(0xFFFFFFFFu, m0, bit)
                                : __shfl_sync(0xFFFFFFFFu, m1, bit - 32);
            rw &= ~mw;
            rw &= ~(1ull << bit);
        }
        __syncwarp();          // ssel visible before next word's fold
    }

    for (int q = cnt + lane; q < NOUT; q += 32)
        ob[q] = make_float4(0.0f, 0.0f, 0.0f, 0.0f);
}

// ---------------- launch ----------------
extern "C" void kernel_launch(void* const* d_in, const int* in_sizes, int n_in,
                              void* d_out, int out_size) {
    const float4* cls4    = (const float4*)d_in[0];
    const float4* bbox    = (const float4*)d_in[1];
    const float4* anchors = (const float4*)d_in[2];
    float4* out = (float4*)d_out;

    (void)in_sizes; (void)n_in; (void)out_size;

    const int total = BATCH * NELEM;

    k_zero<<<(BATCH * BINS / 4) / 256, 256>>>();
    k_hist<<<(total / 4) / 256, 256>>>(cls4);
    k_select<<<BATCH, 1024>>>();
    k_compact<<<(total / 4) / 256, 256>>>(cls4);

    cudaFuncSetAttribute(k_sort, cudaFuncAttributeMaxDynamicSharedMemorySize, 65536);
    k_sort<<<BATCH, 1024, 65536>>>(bbox, anchors);

    dim3 mgrid(TRI_TOTAL, 1, BATCH);
    k_mask<<<mgrid, 256>>>();

    k_seq<<<BATCH, 32>>>(out);
}

// round 13
// speedup vs baseline: 1.4791x; 1.1626x over previous
#include <cuda_runtime.h>
#include <cuda_bf16.h>
#include <cstdint>

// Problem constants
#define BATCH   8
#define NELEM   262144          // 2^18
#define NSHIFT  18
#define TOPK    6000
#define NOUT    1000
#define NMS_THR 0.7f
#define BINS    65536           // scores < 1.0 => (bits>>14) <= 65024
#define BIN_SHIFT 14
#define SORTN   8192
#define NPAD    6016            // 94 * 64
#define NPAD2   (NPAD + 40)     // prefetch overrun padding
#define NWORDS  94
#define RC4N    24              // ceil(94/4)
#define TRI_TOTAL 1152

typedef unsigned long long u64;
typedef unsigned int u32;

// ---------------- static device scratch ----------------
__device__ u32 g_hist[BATCH * BINS];             // 2 MB
__device__ u64 g_main[BATCH * TOPK];
__device__ u64 g_bnd[BATCH * NELEM];
__device__ u32 g_cnt_main[BATCH];
__device__ u32 g_cnt_bnd[BATCH];
__device__ u32 g_pbin[BATCH];

__device__ float4 g_sbox[BATCH][NPAD];           // sorted, decoded, clipped boxes
__device__ float  g_area[BATCH][NPAD];
__device__ u64    g_mask[BATCH][NPAD2][NWORDS];  // suppression bitmasks (upper tri valid)

// triangular grid prefix: tri[r] = 94r - 2r(r-1) (compile-time)
__constant__ u32 c_tri[RC4N] = {
    0, 94, 184, 270, 352, 430, 504, 574, 640, 702, 760, 814,
    864, 910, 952, 990, 1024, 1054, 1080, 1102, 1120, 1134, 1144, 1150
};

// ---------------- kernel 0: zero scratch (vectorized) ----------------
__global__ void k_zero(){
    u32 i = blockIdx.x * blockDim.x + threadIdx.x;        // over uint4 groups
    ((uint4*)g_hist)[i] = make_uint4(0u, 0u, 0u, 0u);
    if (i < BATCH) { g_cnt_main[i] = 0; g_cnt_bnd[i] = 0; }
}

// ---------------- kernel 1: histogram (4 elems/thread) ----------------
__global__ void k_hist(const float4* __restrict__ cls4) {
    u32 i = blockIdx.x * blockDim.x + threadIdx.x;   // group of 4 elements
    float4 p0 = cls4[2 * i];
    float4 p1 = cls4[2 * i + 1];
    u32 b = (i << 2) >> NSHIFT;                      // all 4 in same batch
    u32* h = &g_hist[b * BINS];
    u32 b0 = min(__float_as_uint(p0.y) >> BIN_SHIFT, (u32)(BINS - 1));
    u32 b1 = min(__float_as_uint(p0.w) >> BIN_SHIFT, (u32)(BINS - 1));
    u32 b2 = min(__float_as_uint(p1.y) >> BIN_SHIFT, (u32)(BINS - 1));
    u32 b3 = min(__float_as_uint(p1.w) >> BIN_SHIFT, (u32)(BINS - 1));
    atomicAdd(&h[b0], 1u);
    atomicAdd(&h[b1], 1u);
    atomicAdd(&h[b2], 1u);
    atomicAdd(&h[b3], 1u);
}

// ---------------- kernel 2: find per-batch threshold bin ----------------
__global__ void __launch_bounds__(1024) k_select() {
    int b = blockIdx.x;
    int tid = threadIdx.x;
    const int CH = BINS / 1024;                  // 64 bins per thread
    const u32* hist = &g_hist[b * BINS];

    u32 mysum = 0;
    int base = tid * CH;
    #pragma unroll 8
    for (int k = 0; k < CH; k++) mysum += hist[base + k];

    __shared__ u32 ss[1024];
    ss[tid] = mysum;
    __syncthreads();
    for (int off = 1; off < 1024; off <<= 1) {
        u32 v = (tid + off < 1024) ? ss[tid + off] : 0u;
        __syncthreads();
        ss[tid] += v;
        __syncthreads();
    }
    u32 A = ss[tid] - mysum;                     // strictly-above count
    if (A < TOPK && A + mysum >= TOPK) {
        u32 acc = A;
        for (int bin = base + CH - 1; bin >= base; --bin) {
            u32 h = hist[bin];
            if (acc + h >= TOPK) { g_pbin[b] = (u32)bin; break; }
            acc += h;
        }
    }
}

// ---------------- kernel 3: compaction (4 elems/thread) ----------------
__global__ void k_compact(const float4* __restrict__ cls4) {
    u32 i = blockIdx.x * blockDim.x + threadIdx.x;   // group of 4 elements
    float4 p0 = cls4[2 * i];
    float4 p1 = cls4[2 * i + 1];
    u32 base = i << 2;
    u32 b = base >> NSHIFT;
    u32 p = g_pbin[b];
    float sc[4] = {p0.y, p0.w, p1.y, p1.w};
    #pragma unroll
    for (int k = 0; k < 4; k++) {
        u32 bits = __float_as_uint(sc[k]);
        u32 bin = min(bits >> BIN_SHIFT, (u32)(BINS - 1));
        u32 idx = (base + k) & (NELEM - 1);
        if (bin > p) {
            u32 pos = atomicAdd(&g_cnt_main[b], 1u);
            g_main[b * TOPK + pos] = ((u64)bits << 32) | (u32)(~idx);
        } else if (bin == p) {
            u32 pos = atomicAdd(&g_cnt_bnd[b], 1u);
            g_bnd[(u32)b * NELEM + pos] = ((u64)bits << 32) | (u32)(~idx);
        }
    }
}

// ---------------- kernel 4: sort keys, decode boxes -> global ----------------
// One bitonic compare-exchange micro-step on 8 register-resident elements.
__device__ __forceinline__ void reg_step(u64* e, int base, int k, int j) {
    #pragma unroll
    for (int a = 0; a < 8; a++) {
        if ((a & j) == 0) {
            int p = a | j;
            bool dirDesc = (((base + a) & k) == 0);
            u64 x = e[a], y = e[p];
            if ((x < y) == dirDesc) { e[a] = y; e[p] = x; }
        }
    }
}

__global__ void __launch_bounds__(1024, 1)
k_sort(const float4* __restrict__ bbox, const float4* __restrict__ anchors) {
    extern __shared__ __align__(16) unsigned char smem_raw[];
    u64* keys = (u64*)smem_raw;                  // 8192 * 8 = 65536

    int b = blockIdx.x;
    int tid = threadIdx.x;
    int lane = tid & 31;
    int wid = tid >> 5;

    u32 cnt_main = g_cnt_main[b];
    u32 m = g_cnt_bnd[b];
    u32 total = cnt_main + m;

    for (u32 i = tid; i < cnt_main; i += 1024) keys[i] = g_main[b * TOPK + i];

    if (total <= SORTN) {
        for (u32 i = tid; i < m; i += 1024) keys[cnt_main + i] = g_bnd[(u32)b * NELEM + i];
        for (u32 i = total + tid; i < SORTN; i += 1024) keys[i] = 0ull;
        __syncthreads();
    } else {
        // pathological fallback: iteratively select top-r boundary keys
        for (u32 i = cnt_main + tid; i < SORTN; i += 1024) keys[i] = 0ull;
        __syncthreads();
        __shared__ u64 rk[32];
        __shared__ u32 rp[32];
        int r = TOPK - (int)cnt_main;
        for (int round = 0; round < r; ++round) {
            u64 bk = 0; u32 bp = 0;
            for (u32 i = tid; i < m; i += 1024) {
                u64 v = g_bnd[(u32)b * NELEM + i];
                if (v > bk) { bk = v; bp = i; }
            }
            for (int off = 16; off; off >>= 1) {
                u64 ok = __shfl_down_sync(0xFFFFFFFFu, bk, off);
                u32 op = __shfl_down_sync(0xFFFFFFFFu, bp, off);
                if (ok > bk) { bk = ok; bp = op; }
            }
            if (lane == 0) { rk[wid] = bk; rp[wid] = bp; }
            __syncthreads();
            if (wid == 0) {
                bk = rk[lane]; bp = rp[lane];
                for (int off = 16; off; off >>= 1) {
                    u64 ok = __shfl_down_sync(0xFFFFFFFFu, bk, off);
                    u32 op = __shfl_down_sync(0xFFFFFFFFu, bp, off);
                    if (ok > bk) { bk = ok; bp = op; }
                }
                if (lane == 0) {
                    keys[cnt_main + round] = bk;
                    g_bnd[(u32)b * NELEM + bp] = 0ull;
                }
            }
            __syncthreads();
        }
    }

    // -------- register-blocked bitonic sort (descending) --------
    int rbase = tid * 8;
    u64 e[8];
    {
        // prologue: stages k=2,4,8 entirely in registers
        ulonglong2* kv = reinterpret_cast<ulonglong2*>(keys + rbase);
        ulonglong2 v0 = kv[0], v1 = kv[1], v2 = kv[2], v3 = kv[3];
        e[0]=v0.x; e[1]=v0.y; e[2]=v1.x; e[3]=v1.y;
        e[4]=v2.x; e[5]=v2.y; e[6]=v3.x; e[7]=v3.y;
        reg_step(e, rbase, 2, 1);
        reg_step(e, rbase, 4, 2); reg_step(e, rbase, 4, 1);
        reg_step(e, rbase, 8, 4); reg_step(e, rbase, 8, 2); reg_step(e, rbase, 8, 1);
        kv[0] = make_ulonglong2(e[0], e[1]);
        kv[1] = make_ulonglong2(e[2], e[3]);
        kv[2] = make_ulonglong2(e[4], e[5]);
        kv[3] = make_ulonglong2(e[6], e[7]);
    }
    __syncthreads();

    for (u32 k = 16; k <= SORTN; k <<= 1) {
        for (u32 j = k >> 1; j >= 8; j >>= 1) {
            for (u32 i = tid; i < SORTN; i += 1024) {
                u32 ix = i ^ j;
                if (ix > i) {
                    u64 a = keys[i], c = keys[ix];
                    bool dirDesc = ((i & k) == 0);
                    if ((a < c) == dirDesc) { keys[i] = c; keys[ix] = a; }
                }
            }
            __syncthreads();
        }
        // j = 4,2,1 in registers
        {
            ulonglong2* kv = reinterpret_cast<ulonglong2*>(keys + rbase);
            ulonglong2 v0 = kv[0], v1 = kv[1], v2 = kv[2], v3 = kv[3];
            e[0]=v0.x; e[1]=v0.y; e[2]=v1.x; e[3]=v1.y;
            e[4]=v2.x; e[5]=v2.y; e[6]=v3.x; e[7]=v3.y;
            reg_step(e, rbase, (int)k, 4);
            reg_step(e, rbase, (int)k, 2);
            reg_step(e, rbase, (int)k, 1);
            kv[0] = make_ulonglong2(e[0], e[1]);
            kv[1] = make_ulonglong2(e[2], e[3]);
            kv[2] = make_ulonglong2(e[4], e[5]);
            kv[3] = make_ulonglong2(e[6], e[7]);
        }
        __syncthreads();
    }

    // decode boxes for top slots, write to global (+ zero pad)
    for (int s = tid; s < NPAD; s += 1024) {
        if (s < TOPK) {
            u64 key = keys[s];
            u32 idx = ~(u32)(key & 0xFFFFFFFFull);
            u32 gi = ((u32)b << NSHIFT) + idx;
            float4 a = anchors[gi];
            float4 d = bbox[gi];
            d.x *= 0.1f; d.y *= 0.1f; d.z *= 0.2f; d.w *= 0.2f;
            float h = a.z - a.x;
            float w = a.w - a.y;
            float cy = a.x + 0.5f * h;
            float cx = a.y + 0.5f * w;
            cy = cy + d.x * h;
            cx = cx + d.y * w;
            h = h * expf(d.z);
            w = w * expf(d.w);
            float4 box;
            box.x = fminf(fmaxf(cy - 0.5f * h, 0.0f), 1.0f);
            box.y = fminf(fmaxf(cx - 0.5f * w, 0.0f), 1.0f);
            box.z = fminf(fmaxf(cy + 0.5f * h, 0.0f), 1.0f);
            box.w = fminf(fmaxf(cx + 0.5f * w, 0.0f), 1.0f);
            g_sbox[b][s] = box;
            g_area[b][s] = (box.z - box.x) * (box.w - box.y);
        } else {
            g_sbox[b][s] = make_float4(0.0f, 0.0f, 0.0f, 0.0f);
            g_area[b][s] = 0.0f;
        }
    }
}

// ---------------- kernel 5: pairwise IoU suppression bitmask ----------------
// Triangular grid; division-free fast path with exact near-threshold fixup.
__global__ void __launch_bounds__(256) k_mask() {
    // decode flat triangular index -> (rc4, cc)
    u32 flat = blockIdx.x;
    int rc4 = 0;
    #pragma unroll
    for (int k = 0; k < RC4N; k++) if (flat >= c_tri[k]) rc4 = k;
    int cc = (rc4 << 2) + (int)(flat - c_tri[rc4]);
    int b = blockIdx.z;

    __shared__ float4 cbox[64];
    __shared__ float  ca07[64];      // 0.7 * area
    __shared__ float  ca[64];        // exact area (fallback path)
    int t = threadIdx.x;
    int col0 = cc << 6;
    if (t < 64) {
        cbox[t] = g_sbox[b][col0 + t];
        float ar = g_area[b][col0 + t];
        ca[t] = ar;
        ca07[t] = 0.7f * ar;
    }
    __syncthreads();

    int rc = (rc4 << 2) + (t >> 6);
    if (rc > cc || rc >= NWORDS) return;
    int i = (rc << 6) + (t & 63);
    float4 a = g_sbox[b][i];
    float areaA = g_area[b][i];
    float a07 = 0.7f * areaA;

    u64 bits = 0, nearb = 0;
    if (cc != rc) {
        // off-diagonal: all 64 columns are strictly after row i
        #pragma unroll 16
        for (int j = 0; j < 64; j++) {
            float4 c = cbox[j];
            float y1 = fmaxf(a.x, c.x);
            float x1 = fmaxf(a.y, c.y);
            float y2 = fminf(a.z, c.z);
            float x2 = fminf(a.w, c.w);
            float inter = fmaxf(y2 - y1, 0.0f) * fmaxf(x2 - x1, 0.0f);
            float rhs = a07 + ca07[j];
            float d = fmaf(1.7f, inter, -rhs);
            float mg = fmaf(1e-4f, rhs, 1e-12f);
            if (d > 0.0f) bits |= (1ull << j);
            if (fabsf(d) < mg) nearb |= (1ull << j);
        }
    } else {
        #pragma unroll 16
        for (int j = 0; j < 64; j++) {
            if (col0 + j > i) {
                float4 c = cbox[j];
                float y1 = fmaxf(a.x, c.x);
                float x1 = fmaxf(a.y, c.y);
                float y2 = fminf(a.z, c.z);
                float x2 = fminf(a.w, c.w);
                float inter = fmaxf(y2 - y1, 0.0f) * fmaxf(x2 - x1, 0.0f);
                float rhs = a07 + ca07[j];
                float d = fmaf(1.7f, inter, -rhs);
                float mg = fmaf(1e-4f, rhs, 1e-12f);
                if (d > 0.0f) bits |= (1ull << j);
                if (fabsf(d) < mg) nearb |= (1ull << j);
            }
        }
    }

    // rare exact fixup (reference rounding order, IEEE div)
    while (nearb) {
        int j = __ffsll((long long)nearb) - 1;
        nearb &= nearb - 1;
        float4 c = cbox[j];
        float y1 = fmaxf(a.x, c.x);
        float x1 = fmaxf(a.y, c.y);
        float y2 = fminf(a.z, c.z);
        float x2 = fminf(a.w, c.w);
        float inter = fmaxf(y2 - y1, 0.0f) * fmaxf(x2 - x1, 0.0f);
        float denom = areaA + ca[j] - inter + 1e-9f;
        float iou = inter / denom;
        if (iou > NMS_THR) bits |= (1ull << j);
        else               bits &= ~(1ull << j);
    }

    g_mask[b][i][cc] = bits;
}

// ---------------- kernel 6: serial greedy pass over bitmasks ----------------
// Per-selection critical path is register/shfl ONLY (no memory ops at all):
//   ffs -> shfl(diag word) -> AND -> ffs.
// Selected indices are recorded in SMEM; box gather + output writes happen
// once at the end with full 32-lane parallelism. Row folds into the register
// suppression set occur lazily at word transitions (rows L1-prefetched).
__global__ void __launch_bounds__(32) k_seq(float4* __restrict__ out) {
    int b = blockIdx.x;
    int lane = threadIdx.x;

    __shared__ int sel[NOUT];        // selected candidate indices, in order

    const float4* sb = g_sbox[b];
    float4* ob = out + b * NOUT;

    u64 r0 = 0, r1 = 0, r2 = 0;      // remv words: lane, lane+32, lane+64
    const int j1 = lane, j2 = lane + 32, j3 = lane + 64;
    const bool g3 = (j3 < NWORDS);
    int cnt = 0;
    int fold_from = 0;               // first selection not yet folded

    // prefetch word 0 diagonal gather
    {
        const char* p0 = (const char*)&g_mask[b][lane][0];
        const char* p1 = (const char*)&g_mask[b][32 + lane][0];
        asm volatile("prefetch.global.L1 [%0];" :: "l"(p0));
        asm volatile("prefetch.global.L1 [%0];" :: "l"(p1));
    }

    for (int w = 0; w < NWORDS && cnt < NOUT; w++) {
        // 1) issue this word's diagonal gather (consumed after the fold)
        u64 m0 = g_mask[b][(w << 6) + lane][w];
        u64 m1 = g_mask[b][(w << 6) + 32 + lane][w];

        // 2) fold pending rows (selections since last fold), 4-way MLP
        int k = fold_from;
        for (; k + 4 <= cnt; k += 4) {
            const u64* p0 = &g_mask[b][sel[k]][0];
            const u64* p1 = &g_mask[b][sel[k + 1]][0];
            const u64* p2 = &g_mask[b][sel[k + 2]][0];
            const u64* p3 = &g_mask[b][sel[k + 3]][0];
            u64 a0 = p0[j1], a1 = p1[j1], a2 = p2[j1], a3 = p3[j1];
            u64 b0 = p0[j2], b1 = p1[j2], b2 = p2[j2], b3 = p3[j2];
            u64 c0 = 0, c1 = 0, c2 = 0, c3 = 0;
            if (g3) { c0 = p0[j3]; c1 = p1[j3]; c2 = p2[j3]; c3 = p3[j3]; }
            r0 |= a0 | a1 | a2 | a3;
            r1 |= b0 | b1 | b2 | b3;
            r2 |= c0 | c1 | c2 | c3;
        }
        for (; k < cnt; k++) {
            const u64* p0 = &g_mask[b][sel[k]][0];
            r0 |= p0[j1];
            r1 |= p0[j2];
            if (g3) r2 |= p0[j3];
        }
        fold_from = cnt;

        // 3) remaining-candidates word from register remv
        u64 rv;
        if (w < 32)      rv = __shfl_sync(0xFFFFFFFFu, r0, w);
        else if (w < 64) rv = __shfl_sync(0xFFFFFFFFu, r1, w - 32);
        else             rv = __shfl_sync(0xFFFFFFFFu, r2, w - 64);
        u64 live = (w == NWORDS - 1) ? ((1ull << 48) - 1ull) : ~0ull;
        u64 rw = (~rv) & live;

        // 4) prefetch next word's diagonal gather
        if (w + 1 < NWORDS) {
            const char* p0 = (const char*)&g_mask[b][((w + 1) << 6) + lane][w + 1];
            const char* p1 = (const char*)&g_mask[b][((w + 1) << 6) + 32 + lane][w + 1];
            asm volatile("prefetch.global.L1 [%0];" :: "l"(p0));
            asm volatile("prefetch.global.L1 [%0];" :: "l"(p1));
        }
        if (!rw) continue;

        // 5) selection loop: NO memory on the critical path
        while (rw && cnt < NOUT) {
            int bit = __ffsll((long long)rw) - 1;
            int i = (w << 6) + bit;

            if (lane == 0) sel[cnt] = i;   // STS, fire-and-forget
            cnt++;

            // prefetch row i for the next fold (94 words = 6 lines)
            if (lane < 6) {
                const char* p = (const char*)&g_mask[b][i][0] + (u32)lane * 128;
                asm volatile("prefetch.global.L1 [%0];" :: "l"(p));
            }

            u64 mw = (bit < 32) ? __shfl_sync(0xFFFFFFFFu, m0, bit)
                                : __shfl_sync(0xFFFFFFFFu, m1, bit - 32);
            rw &= ~mw;
            rw &= ~(1ull << bit);
        }
        __syncwarp();          // sel visible before next fold
    }
    __syncwarp();

    // gather + write outputs with full lane parallelism
    for (int q = lane; q < cnt; q += 32)
        ob[q] = sb[sel[q]];
    for (int q = cnt + lane; q < NOUT; q += 32)
        ob[q] = make_float4(0.0f, 0.0f, 0.0f, 0.0f);
}

// ---------------- launch ----------------
extern "C" void kernel_launch(void* const* d_in, const int* in_sizes, int n_in,
                              void* d_out, int out_size) {
    const float4* cls4    = (const float4*)d_in[0];
    const float4* bbox    = (const float4*)d_in[1];
    const float4* anchors = (const float4*)d_in[2];
    float4* out = (float4*)d_out;

    (void)in_sizes; (void)n_in; (void)out_size;

    const int total = BATCH * NELEM;

    k_zero<<<(BATCH * BINS / 4) / 256, 256>>>();
    k_hist<<<(total / 4) / 256, 256>>>(cls4);
    k_select<<<BATCH, 1024>>>();
    k_compact<<<(total / 4) / 256, 256>>>(cls4);

    cudaFuncSetAttribute(k_sort, cudaFuncAttributeMaxDynamicSharedMemorySize, 65536);
    k_sort<<<BATCH, 1024, 65536>>>(bbox, anchors);

    dim3 mgrid(TRI_TOTAL, 1, BATCH);
    k_mask<<<mgrid, 256>>>();

    k_seq<<<BATCH, 32>>>(out);
}

// round 15
// speedup vs baseline: 1.5207x; 1.0281x over previous
#include <cuda_runtime.h>
#include <cuda_bf16.h>
#include <cstdint>

// Problem constants
#define BATCH   8
#define NELEM   262144          // 2^18
#define NSHIFT  18
#define TOPK    6000
#define NOUT    1000
#define NMS_THR 0.7f
#define BINS    65536           // scores < 1.0 => (bits>>14) <= 65024
#define BIN_SHIFT 14
#define SORTN   8192
#define NPAD    6016            // 94 * 64
#define NPAD2   (NPAD + 40)     // prefetch overrun padding
#define NWORDS  94
#define RC4N    24              // ceil(94/4)
#define TRI_TOTAL 1152

typedef unsigned long long u64;
typedef unsigned int u32;

// ---------------- static device scratch ----------------
__device__ u32 g_hist[BATCH * BINS];             // 2 MB
__device__ u64 g_main[BATCH * TOPK];
__device__ u64 g_bnd[BATCH * NELEM];
__device__ u32 g_cnt_main[BATCH];
__device__ u32 g_cnt_bnd[BATCH];
__device__ u32 g_pbin[BATCH];

__device__ float4 g_sbox[BATCH][NPAD];           // sorted, decoded, clipped boxes
__device__ float  g_area[BATCH][NPAD];
__device__ u64    g_mask[BATCH][NPAD2][NWORDS];  // suppression bitmasks (upper tri valid)

// triangular grid prefix: tri[r] = 94r - 2r(r-1) (compile-time)
__constant__ u32 c_tri[RC4N] = {
    0, 94, 184, 270, 352, 430, 504, 574, 640, 702, 760, 814,
    864, 910, 952, 990, 1024, 1054, 1080, 1102, 1120, 1134, 1144, 1150
};

// ---------------- kernel 0: zero scratch (vectorized) ----------------
__global__ void k_zero(){
    u32 i = blockIdx.x * blockDim.x + threadIdx.x;        // over uint4 groups
    ((uint4*)g_hist)[i] = make_uint4(0u, 0u, 0u, 0u);
    if (i < BATCH) { g_cnt_main[i] = 0; g_cnt_bnd[i] = 0; }
}

// ---------------- kernel 1: histogram (4 elems/thread) ----------------
__global__ void k_hist(const float4* __restrict__ cls4) {
    u32 i = blockIdx.x * blockDim.x + threadIdx.x;   // group of 4 elements
    float4 p0 = cls4[2 * i];
    float4 p1 = cls4[2 * i + 1];
    u32 b = (i << 2) >> NSHIFT;                      // all 4 in same batch
    u32* h = &g_hist[b * BINS];
    u32 b0 = min(__float_as_uint(p0.y) >> BIN_SHIFT, (u32)(BINS - 1));
    u32 b1 = min(__float_as_uint(p0.w) >> BIN_SHIFT, (u32)(BINS - 1));
    u32 b2 = min(__float_as_uint(p1.y) >> BIN_SHIFT, (u32)(BINS - 1));
    u32 b3 = min(__float_as_uint(p1.w) >> BIN_SHIFT, (u32)(BINS - 1));
    atomicAdd(&h[b0], 1u);
    atomicAdd(&h[b1], 1u);
    atomicAdd(&h[b2], 1u);
    atomicAdd(&h[b3], 1u);
}

// ---------------- kernel 2: find per-batch threshold bin ----------------
__global__ void __launch_bounds__(1024) k_select() {
    int b = blockIdx.x;
    int tid = threadIdx.x;
    const int CH = BINS / 1024;                  // 64 bins per thread
    const u32* hist = &g_hist[b * BINS];

    u32 mysum = 0;
    int base = tid * CH;
    #pragma unroll 8
    for (int k = 0; k < CH; k++) mysum += hist[base + k];

    __shared__ u32 ss[1024];
    ss[tid] = mysum;
    __syncthreads();
    for (int off = 1; off < 1024; off <<= 1) {
        u32 v = (tid + off < 1024) ? ss[tid + off] : 0u;
        __syncthreads();
        ss[tid] += v;
        __syncthreads();
    }
    u32 A = ss[tid] - mysum;                     // strictly-above count
    if (A < TOPK && A + mysum >= TOPK) {
        u32 acc = A;
        for (int bin = base + CH - 1; bin >= base; --bin) {
            u32 h = hist[bin];
            if (acc + h >= TOPK) { g_pbin[b] = (u32)bin; break; }
            acc += h;
        }
    }
}

// ---------------- kernel 3: compaction (4 elems/thread) ----------------
__global__ void k_compact(const float4* __restrict__ cls4) {
    u32 i = blockIdx.x * blockDim.x + threadIdx.x;   // group of 4 elements
    float4 p0 = cls4[2 * i];
    float4 p1 = cls4[2 * i + 1];
    u32 base = i << 2;
    u32 b = base >> NSHIFT;
    u32 p = g_pbin[b];
    float sc[4] = {p0.y, p0.w, p1.y, p1.w};
    #pragma unroll
    for (int k = 0; k < 4; k++) {
        u32 bits = __float_as_uint(sc[k]);
        u32 bin = min(bits >> BIN_SHIFT, (u32)(BINS - 1));
        u32 idx = (base + k) & (NELEM - 1);
        if (bin > p) {
            u32 pos = atomicAdd(&g_cnt_main[b], 1u);
            g_main[b * TOPK + pos] = ((u64)bits << 32) | (u32)(~idx);
        } else if (bin == p) {
            u32 pos = atomicAdd(&g_cnt_bnd[b], 1u);
            g_bnd[(u32)b * NELEM + pos] = ((u64)bits << 32) | (u32)(~idx);
        }
    }
}

// ---------------- kernel 4: sort keys, decode boxes -> global ----------------
// One bitonic compare-exchange micro-step on 8 register-resident elements.
__device__ __forceinline__ void reg_step(u64* e, int base, int k, int j) {
    #pragma unroll
    for (int a = 0; a < 8; a++) {
        if ((a & j) == 0) {
            int p = a | j;
            bool dirDesc = (((base + a) & k) == 0);
            u64 x = e[a], y = e[p];
            if ((x < y) == dirDesc) { e[a] = y; e[p] = x; }
        }
    }
}

// Stage (k,j) with j in {8..128}: same-slot exchange between lanes t and
// t^(j/8) — pure shfl, no smem, no barrier. Comparator network identical
// to the smem pass it replaces.
__device__ __forceinline__ void shfl_stage(u64* e, int tid, u32 k, u32 j) {
    int d = (int)(j >> 3);                            // lane xor distance
    bool dirDesc = ((((u32)tid << 3) & k) == 0);      // (i & k)==0, a-independent
    bool lo = (((u32)tid & (u32)d) == 0);             // (i & j)==0
    bool keepMax = (dirDesc == lo);
    #pragma unroll
    for (int a = 0; a < 8; a++) {
        u64 o = __shfl_xor_sync(0xFFFFFFFFu, e[a], d);
        u64 mx = (e[a] > o) ? e[a] : o;
        u64 mn = (e[a] > o) ? o : e[a];
        e[a] = keepMax ? mx : mn;
    }
}

__global__ void __launch_bounds__(1024, 1)
k_sort(const float4* __restrict__ bbox, const float4* __restrict__ anchors) {
    extern __shared__ __align__(16) unsigned char smem_raw[];
    u64* keys = (u64*)smem_raw;                  // 8192 * 8 = 65536

    int b = blockIdx.x;
    int tid = threadIdx.x;
    int lane = tid & 31;
    int wid = tid >> 5;

    u32 cnt_main = g_cnt_main[b];
    u32 m = g_cnt_bnd[b];
    u32 total = cnt_main + m;

    for (u32 i = tid; i < cnt_main; i += 1024) keys[i] = g_main[b * TOPK + i];

    if (total <= SORTN) {
        for (u32 i = tid; i < m; i += 1024) keys[cnt_main + i] = g_bnd[(u32)b * NELEM + i];
        for (u32 i = total + tid; i < SORTN; i += 1024) keys[i] = 0ull;
        __syncthreads();
    } else {
        // pathological fallback: iteratively select top-r boundary keys
        for (u32 i = cnt_main + tid; i < SORTN; i += 1024) keys[i] = 0ull;
        __syncthreads();
        __shared__ u64 rk[32];
        __shared__ u32 rp[32];
        int r = TOPK - (int)cnt_main;
        for (int round = 0; round < r; ++round) {
            u64 bk = 0; u32 bp = 0;
            for (u32 i = tid; i < m; i += 1024) {
                u64 v = g_bnd[(u32)b * NELEM + i];
                if (v > bk) { bk = v; bp = i; }
            }
            for (int off = 16; off; off >>= 1) {
                u64 ok = __shfl_down_sync(0xFFFFFFFFu, bk, off);
                u32 op = __shfl_down_sync(0xFFFFFFFFu, bp, off);
                if (ok > bk) { bk = ok; bp = op; }
            }
            if (lane == 0) { rk[wid] = bk; rp[wid] = bp; }
            __syncthreads();
            if (wid == 0) {
                bk = rk[lane]; bp = rp[lane];
                for (int off = 16; off; off >>= 1) {
                    u64 ok = __shfl_down_sync(0xFFFFFFFFu, bk, off);
                    u32 op = __shfl_down_sync(0xFFFFFFFFu, bp, off);
                    if (ok > bk) { bk = ok; bp = op; }
                }
                if (lane == 0) {
                    keys[cnt_main + round] = bk;
                    g_bnd[(u32)b * NELEM + bp] = 0ull;
                }
            }
            __syncthreads();
        }
    }

    // -------- register/shfl-blocked bitonic sort (descending) --------
    int rbase = tid * 8;
    u64 e[8];
    ulonglong2* kv = reinterpret_cast<ulonglong2*>(keys + rbase);

    // load slice; stages k=2..256 entirely register/shfl resident (no barriers)
    {
        ulonglong2 v0 = kv[0], v1 = kv[1], v2 = kv[2], v3 = kv[3];
        e[0]=v0.x; e[1]=v0.y; e[2]=v1.x; e[3]=v1.y;
        e[4]=v2.x; e[5]=v2.y; e[6]=v3.x; e[7]=v3.y;
    }
    reg_step(e, rbase, 2, 1);
    reg_step(e, rbase, 4, 2); reg_step(e, rbase, 4, 1);
    reg_step(e, rbase, 8, 4); reg_step(e, rbase, 8, 2); reg_step(e, rbase, 8, 1);
    for (u32 k = 16; k <= 256; k <<= 1) {
        for (u32 j = k >> 1; j >= 8; j >>= 1) shfl_stage(e, tid, k, j);
        reg_step(e, rbase, (int)k, 4);
        reg_step(e, rbase, (int)k, 2);
        reg_step(e, rbase, (int)k, 1);
    }
    kv[0] = make_ulonglong2(e[0], e[1]);
    kv[1] = make_ulonglong2(e[2], e[3]);
    kv[2] = make_ulonglong2(e[4], e[5]);
    kv[3] = make_ulonglong2(e[6], e[7]);
    __syncthreads();

    // k = 512..8192: smem passes only for j >= 256 (cross-warp)
    for (u32 k = 512; k <= SORTN; k <<= 1) {
        for (u32 j = k >> 1; j >= 256; j >>= 1) {
            for (u32 i = tid; i < SORTN; i += 1024) {
                u32 ix = i ^ j;
                if (ix > i) {
                    u64 a = keys[i], c = keys[ix];
                    bool dirDesc = ((i & k) == 0);
                    if ((a < c) == dirDesc) { keys[i] = c; keys[ix] = a; }
                }
            }
            __syncthreads();
        }
        // j = 128..8 via shfl, j = 4,2,1 in registers
        {
            ulonglong2 v0 = kv[0], v1 = kv[1], v2 = kv[2], v3 = kv[3];
            e[0]=v0.x; e[1]=v0.y; e[2]=v1.x; e[3]=v1.y;
            e[4]=v2.x; e[5]=v2.y; e[6]=v3.x; e[7]=v3.y;
        }
        for (u32 j = 128; j >= 8; j >>= 1) shfl_stage(e, tid, k, j);
        reg_step(e, rbase, (int)k, 4);
        reg_step(e, rbase, (int)k, 2);
        reg_step(e, rbase, (int)k, 1);
        kv[0] = make_ulonglong2(e[0], e[1]);
        kv[1] = make_ulonglong2(e[2], e[3]);
        kv[2] = make_ulonglong2(e[4], e[5]);
        kv[3] = make_ulonglong2(e[6], e[7]);
        __syncthreads();
    }

    // decode boxes for top slots, write to global (+ zero pad)
    for (int s = tid; s < NPAD; s += 1024) {
        if (s < TOPK) {
            u64 key = keys[s];
            u32 idx = ~(u32)(key & 0xFFFFFFFFull);
            u32 gi = ((u32)b << NSHIFT) + idx;
            float4 a = anchors[gi];
            float4 d = bbox[gi];
            d.x *= 0.1f; d.y *= 0.1f; d.z *= 0.2f; d.w *= 0.2f;
            float h = a.z - a.x;
            float w = a.w - a.y;
            float cy = a.x + 0.5f * h;
            float cx = a.y + 0.5f * w;
            cy = cy + d.x * h;
            cx = cx + d.y * w;
            h = h * expf(d.z);
            w = w * expf(d.w);
            float4 box;
            box.x = fminf(fmaxf(cy - 0.5f * h, 0.0f), 1.0f);
            box.y = fminf(fmaxf(cx - 0.5f * w, 0.0f), 1.0f);
            box.z = fminf(fmaxf(cy + 0.5f * h, 0.0f), 1.0f);
            box.w = fminf(fmaxf(cx + 0.5f * w, 0.0f), 1.0f);
            g_sbox[b][s] = box;
            g_area[b][s] = (box.z - box.x) * (box.w - box.y);
        } else {
            g_sbox[b][s] = make_float4(0.0f, 0.0f, 0.0f, 0.0f);
            g_area[b][s] = 0.0f;
        }
    }
}

// ---------------- kernel 5: pairwise IoU suppression bitmask ----------------
// Triangular grid; division-free fast path with exact near-threshold fixup.
__global__ void __launch_bounds__(256) k_mask() {
    // decode flat triangular index -> (rc4, cc)
    u32 flat = blockIdx.x;
    int rc4 = 0;
    #pragma unroll
    for (int k = 0; k < RC4N; k++) if (flat >= c_tri[k]) rc4 = k;
    int cc = (rc4 << 2) + (int)(flat - c_tri[rc4]);
    int b = blockIdx.z;

    __shared__ float4 cbox[64];
    __shared__ float  ca07[64];      // 0.7 * area
    __shared__ float  ca[64];        // exact area (fallback path)
    int t = threadIdx.x;
    int col0 = cc << 6;
    if (t < 64) {
        cbox[t] = g_sbox[b][col0 + t];
        float ar = g_area[b][col0 + t];
        ca[t] = ar;
        ca07[t] = 0.7f * ar;
    }
    __syncthreads();

    int rc = (rc4 << 2) + (t >> 6);
    if (rc > cc || rc >= NWORDS) return;
    int i = (rc << 6) + (t & 63);
    float4 a = g_sbox[b][i];
    float areaA = g_area[b][i];
    float a07 = 0.7f * areaA;

    u64 bits = 0, nearb = 0;
    if (cc != rc) {
        // off-diagonal: all 64 columns are strictly after row i
        #pragma unroll 16
        for (int j = 0; j < 64; j++) {
            float4 c = cbox[j];
            float y1 = fmaxf(a.x, c.x);
            float x1 = fmaxf(a.y, c.y);
            float y2 = fminf(a.z, c.z);
            float x2 = fminf(a.w, c.w);
            float inter = fmaxf(y2 - y1, 0.0f) * fmaxf(x2 - x1, 0.0f);
            float rhs = a07 + ca07[j];
            float d = fmaf(1.7f, inter, -rhs);
            float mg = fmaf(1e-4f, rhs, 1e-12f);
            if (d > 0.0f) bits |= (1ull << j);
            if (fabsf(d) < mg) nearb |= (1ull << j);
        }
    } else {
        #pragma unroll 16
        for (int j = 0; j < 64; j++) {
            if (col0 + j > i) {
                float4 c = cbox[j];
                float y1 = fmaxf(a.x, c.x);
                float x1 = fmaxf(a.y, c.y);
                float y2 = fminf(a.z, c.z);
                float x2 = fminf(a.w, c.w);
                float inter = fmaxf(y2 - y1, 0.0f) * fmaxf(x2 - x1, 0.0f);
                float rhs = a07 + ca07[j];
                float d = fmaf(1.7f, inter, -rhs);
                float mg = fmaf(1e-4f, rhs, 1e-12f);
                if (d > 0.0f) bits |= (1ull << j);
                if (fabsf(d) < mg) nearb |= (1ull << j);
            }
        }
    }

    // rare exact fixup (reference rounding order, IEEE div)
    while (nearb) {
        int j = __ffsll((long long)nearb) - 1;
        nearb &= nearb - 1;
        float4 c = cbox[j];
        float y1 = fmaxf(a.x, c.x);
        float x1 = fmaxf(a.y, c.y);
        float y2 = fminf(a.z, c.z);
        float x2 = fminf(a.w, c.w);
        float inter = fmaxf(y2 - y1, 0.0f) * fmaxf(x2 - x1, 0.0f);
        float denom = areaA + ca[j] - inter + 1e-9f;
        float iou = inter / denom;
        if (iou > NMS_THR) bits |= (1ull << j);
        else               bits &= ~(1ull << j);
    }

    g_mask[b][i][cc] = bits;
}

// ---------------- kernel 6: serial greedy pass over bitmasks ----------------
// Per-selection critical path is register/shfl ONLY (no memory ops at all):
//   ffs -> shfl(diag word) -> AND -> ffs.
// Selected indices are recorded in SMEM; box gather + output writes happen
// once at the end with full 32-lane parallelism. Row folds into the register
// suppression set occur lazily at word transitions (rows L1-prefetched).
__global__ void __launch_bounds__(32) k_seq(float4* __restrict__ out) {
    int b = blockIdx.x;
    int lane = threadIdx.x;

    __shared__ int sel[NOUT];        // selected candidate indices, in order

    const float4* sb = g_sbox[b];
    float4* ob = out + b * NOUT;

    u64 r0 = 0, r1 = 0, r2 = 0;      // remv words: lane, lane+32, lane+64
    const int j1 = lane, j2 = lane + 32, j3 = lane + 64;
    const bool g3 = (j3 < NWORDS);
    int cnt = 0;
    int fold_from = 0;               // first selection not yet folded

    // prefetch word 0 diagonal gather
    {
        const char* p0 = (const char*)&g_mask[b][lane][0];
        const char* p1 = (const char*)&g_mask[b][32 + lane][0];
        asm volatile("prefetch.global.L1 [%0];" :: "l"(p0));
        asm volatile("prefetch.global.L1 [%0];" :: "l"(p1));
    }

    for (int w = 0; w < NWORDS && cnt < NOUT; w++) {
        // 1) issue this word's diagonal gather (consumed after the fold)
        u64 m0 = g_mask[b][(w << 6) + lane][w];
        u64 m1 = g_mask[b][(w << 6) + 32 + lane][w];

        // 2) fold pending rows (selections since last fold), 4-way MLP
        int k = fold_from;
        for (; k + 4 <= cnt; k += 4) {
            const u64* p0 = &g_mask[b][sel[k]][0];
            const u64* p1 = &g_mask[b][sel[k + 1]][0];
            const u64* p2 = &g_mask[b][sel[k + 2]][0];
            const u64* p3 = &g_mask[b][sel[k + 3]][0];
            u64 a0 = p0[j1], a1 = p1[j1], a2 = p2[j1], a3 = p3[j1];
            u64 b0 = p0[j2], b1 = p1[j2], b2 = p2[j2], b3 = p3[j2];
            u64 c0 = 0, c1 = 0, c2 = 0, c3 = 0;
            if (g3) { c0 = p0[j3]; c1 = p1[j3]; c2 = p2[j3]; c3 = p3[j3]; }
            r0 |= a0 | a1 | a2 | a3;
            r1 |= b0 | b1 | b2 | b3;
            r2 |= c0 | c1 | c2 | c3;
        }
        for (; k < cnt; k++) {
            const u64* p0 = &g_mask[b][sel[k]][0];
            r0 |= p0[j1];
            r1 |= p0[j2];
            if (g3) r2 |= p0[j3];
        }
        fold_from = cnt;

        // 3) remaining-candidates word from register remv
        u64 rv;
        if (w < 32)      rv = __shfl_sync(0xFFFFFFFFu, r0, w);
        else if (w < 64) rv = __shfl_sync(0xFFFFFFFFu, r1, w - 32);
        else             rv = __shfl_sync(0xFFFFFFFFu, r2, w - 64);
        u64 live = (w == NWORDS - 1) ? ((1ull << 48) - 1ull) : ~0ull;
        u64 rw = (~rv) & live;

        // 4) prefetch next word's diagonal gather
        if (w + 1 < NWORDS) {
            const char* p0 = (const char*)&g_mask[b][((w + 1) << 6) + lane][w + 1];
            const char* p1 = (const char*)&g_mask[b][((w + 1) << 6) + 32 + lane][w + 1];
            asm volatile("prefetch.global.L1 [%0];" :: "l"(p0));
            asm volatile("prefetch.global.L1 [%0];" :: "l"(p1));
        }
        if (!rw) continue;

        // 5) selection loop: NO memory on the critical path
        while (rw && cnt < NOUT) {
            int bit = __ffsll((long long)rw) - 1;
            int i = (w << 6) + bit;

            if (lane == 0) sel[cnt] = i;   // STS, fire-and-forget
            cnt++;

            // prefetch row i for the next fold (94 words = 6 lines)
            if (lane < 6) {
                const char* p = (const char*)&g_mask[b][i][0] + (u32)lane * 128;
                asm volatile("prefetch.global.L1 [%0];" :: "l"(p));
            }

            u64 mw = (bit < 32) ? __shfl_sync(0xFFFFFFFFu, m0, bit)
                                : __shfl_sync(0xFFFFFFFFu, m1, bit - 32);
            rw &= ~mw;
            rw &= ~(1ull << bit);
        }
        __syncwarp();          // sel visible before next fold
    }
    __syncwarp();

    // gather + write outputs with full lane parallelism
    for (int q = lane; q < cnt; q += 32)
        ob[q] = sb[sel[q]];
    for (int q = cnt + lane; q < NOUT; q += 32)
        ob[q] = make_float4(0.0f, 0.0f, 0.0f, 0.0f);
}

// ---------------- launch ----------------
extern "C" void kernel_launch(void* const* d_in, const int* in_sizes, int n_in,
                              void* d_out, int out_size) {
    const float4* cls4    = (const float4*)d_in[0];
    const float4* bbox    = (const float4*)d_in[1];
    const float4* anchors = (const float4*)d_in[2];
    float4* out = (float4*)d_out;

    (void)in_sizes; (void)n_in; (void)out_size;

    const int total = BATCH * NELEM;

    k_zero<<<(BATCH * BINS / 4) / 256, 256>>>();
    k_hist<<<(total / 4) / 256, 256>>>(cls4);
    k_select<<<BATCH, 1024>>>();
    k_compact<<<(total / 4) / 256, 256>>>(cls4);

    cudaFuncSetAttribute(k_sort, cudaFuncAttributeMaxDynamicSharedMemorySize, 65536);
    k_sort<<<BATCH, 1024, 65536>>>(bbox, anchors);

    dim3 mgrid(TRI_TOTAL, 1, BATCH);
    k_mask<<<mgrid, 256>>>();

    k_seq<<<BATCH, 32>>>(out);
}